// round 3
// baseline (speedup 1.0000x reference)
#include <cuda_runtime.h>
#include <cstdint>

// ---------------- problem constants ----------------
#define NB   8
#define NT   336
#define NN   1024
#define FREQ 42
#define SEG  8
#define DC   64
#define DM   128
#define TREC 41          // FREQ-1, stconv time length for rec path
#define NSTEP 12
#define MAXK 11
#define ALPHA 0.05f

// ---------------- scratch layout (floats) ----------------
// all sizes multiples of 64
static const size_t OFF_A1   = 0;                        // 1024*1024
static const size_t OFF_A2   = OFF_A1   + 1048576;
static const size_t OFF_WCT  = OFF_A2   + 1048576;       // 11*64*64
static const size_t OFF_BSUM = OFF_WCT  + 45056;         // 64
static const size_t OFF_RES  = OFF_BSUM + 64;            // 8*42*1024*64
static const size_t OFF_CONV = OFF_RES  + 22020096;      // 8*41*1024*64
static const size_t OFF_H1A  = OFF_CONV + 21495808;
static const size_t OFF_H2A  = OFF_H1A  + 21495808;
static const size_t OFF_H1B  = OFF_H2A  + 21495808;
static const size_t OFF_H2B  = OFF_H1B  + 21495808;
static const size_t OFF_STOUT= OFF_H2B  + 21495808;
static const size_t OFF_CUR  = OFF_STOUT+ 21495808;      // 8*23*1024*64
static const size_t OFF_TCL  = OFF_CUR  + 12058624;      // 8*1024*64
static const size_t OFF_PH1A = OFF_TCL  + 524288;
static const size_t OFF_PH1B = OFF_PH1A + 524288;
static const size_t OFF_PH2A = OFF_PH1B + 524288;
static const size_t OFF_PH2B = OFF_PH2A + 524288;
static const size_t SCRATCH_TOTAL = OFF_PH2B + 524288;   // 167,817,280 floats

__device__ float g_scratch[SCRATCH_TOTAL];

// ================= common 64x64x64 GEMM micro-kernel =================
// 256 threads, 4x4 microtile per thread, shared tiles stored k-major, pad 68.

__device__ __forceinline__ void loadA_T(float (*As)[68], const float* __restrict__ src,
                                        int ld, int tid) {
    // src: tile origin, rows m (0..63) x k contiguous (64)
#pragma unroll
    for (int i = 0; i < 4; i++) {
        int li = tid + i * 256;
        int r = li >> 4, c4 = li & 15;
        float4 v = *(const float4*)&src[(size_t)r * ld + c4 * 4];
        As[c4 * 4 + 0][r] = v.x;
        As[c4 * 4 + 1][r] = v.y;
        As[c4 * 4 + 2][r] = v.z;
        As[c4 * 4 + 3][r] = v.w;
    }
}

__device__ __forceinline__ void loadB_D(float (*Bs)[68], const float* __restrict__ src,
                                        int ld, int tid) {
    // src: tile origin, rows k (0..63) x n contiguous (64)
#pragma unroll
    for (int i = 0; i < 4; i++) {
        int li = tid + i * 256;
        int r = li >> 4, c4 = li & 15;
        *(float4*)&Bs[r][c4 * 4] = *(const float4*)&src[(size_t)r * ld + c4 * 4];
    }
}

__device__ __forceinline__ void mm64(const float (*As)[68], const float (*Bs)[68],
                                     float acc[4][4], int tx, int ty) {
#pragma unroll
    for (int k = 0; k < 64; k++) {
        float4 a = *(const float4*)&As[k][ty * 4];
        float4 b = *(const float4*)&Bs[k][tx * 4];
        float av[4] = {a.x, a.y, a.z, a.w};
        float bv[4] = {b.x, b.y, b.z, b.w};
#pragma unroll
        for (int i = 0; i < 4; i++)
#pragma unroll
            for (int j = 0; j < 4; j++)
                acc[i][j] = fmaf(av[i], bv[j], acc[i][j]);
    }
}

// ================= adjacency normalization =================
__global__ void k_norm_adj(const float* __restrict__ adj,
                           float* __restrict__ a1, float* __restrict__ a2) {
    int v = blockIdx.x;
    int tid = threadIdx.x;
    __shared__ float r1[256], r2[256];
    float s1 = 0.f, s2 = 0.f;
    for (int n = tid; n < NN; n += 256) {
        s1 += adj[(size_t)v * NN + n];
        s2 += adj[(size_t)n * NN + v];
    }
    r1[tid] = s1; r2[tid] = s2;
    __syncthreads();
    for (int off = 128; off > 0; off >>= 1) {
        if (tid < off) { r1[tid] += r1[tid + off]; r2[tid] += r2[tid + off]; }
        __syncthreads();
    }
    float inv1 = 1.f / (r1[0] + 1.f);
    float inv2 = 1.f / (r2[0] + 1.f);
    for (int n = tid; n < NN; n += 256) {
        float d = (n == v) ? 1.f : 0.f;
        a1[(size_t)v * NN + n] = (adj[(size_t)v * NN + n] + d) * inv1;
        a2[(size_t)v * NN + n] = (adj[(size_t)n * NN + v] + d) * inv2;
    }
}

// ================= combine conv weights =================
// wcT[dt][c][o] = sum_{i >= |dt-5|} conv_wi[o][c][dt-5+i] ; bsum[o] = sum_i b_i[o]
__global__ void k_comb_w(const float* w0, const float* w1, const float* w2,
                         const float* w3, const float* w4, const float* w5,
                         const float* cb0, const float* cb1, const float* cb2,
                         const float* cb3, const float* cb4, const float* cb5,
                         float* __restrict__ wcT, float* __restrict__ bsum) {
    int idx = blockIdx.x * 256 + threadIdx.x;
    if (idx >= 11 * 64 * 64) return;
    int o = idx & 63;
    int c = (idx >> 6) & 63;
    int dt = idx >> 12;
    int dv = dt - 5;
    int ad = dv < 0 ? -dv : dv;
    const float* ws[6] = {w0, w1, w2, w3, w4, w5};
    float acc = 0.f;
    for (int i = ad; i < 6; i++) {
        int K = 2 * i + 1;
        acc += ws[i][(size_t)(o * 64 + c) * K + (dv + i)];
    }
    wcT[((size_t)dt * 64 + c) * 64 + o] = acc;
    if (dt == 0 && c == 0)
        bsum[o] = cb0[o] + cb1[o] + cb2[o] + cb3[o] + cb4[o] + cb5[o];
}

// ================= encoder MLP: (B,42,N,8) -> (B,42,N,64) =================
__global__ void __launch_bounds__(256) k_enc(const float* __restrict__ x,
        const float* __restrict__ w1, const float* __restrict__ b1,
        const float* __restrict__ w2, const float* __restrict__ b2,
        float* __restrict__ out) {
    int n0 = blockIdx.x * 64;
    int f  = blockIdx.y;
    int b  = blockIdx.z;
    __shared__ float xs[64][8];
    __shared__ float hs[64][129];
    __shared__ float w1s[8 * 128];
    int tid = threadIdx.x;
    for (int i = tid; i < 1024; i += 256) w1s[i] = w1[i];
    for (int i = tid; i < 512; i += 256) {
        int s = i >> 6, r = i & 63;
        xs[r][s] = x[((size_t)(b * NT) + f * SEG + s) * NN + n0 + r];
    }
    __syncthreads();
    {
        int r = tid >> 2;
        int j0 = (tid & 3) * 32;
        float xv[8];
#pragma unroll
        for (int s = 0; s < 8; s++) xv[s] = xs[r][s];
        for (int j = j0; j < j0 + 32; j++) {
            float h = b1[j];
#pragma unroll
            for (int s = 0; s < 8; s++) h = fmaf(xv[s], w1s[s * 128 + j], h);
            hs[r][j] = fmaxf(h, 0.f);
        }
    }
    __syncthreads();
    {
        int r = tid >> 2;
        int d0 = (tid & 3) * 16;
        for (int d = d0; d < d0 + 16; d++) {
            float acc = b2[d];
#pragma unroll
            for (int j = 0; j < 128; j++) acc = fmaf(hs[r][j], w2[j * 64 + d], acc);
            out[(((size_t)b * FREQ + f) * NN + n0 + r) * 64 + d] = acc;
        }
    }
}

// ================= t_inception (rec path) =================
// out[b,t,n,:] = (bsum + sum_dt Wc[dt] @ res[b,t+dt-5,n,:]) / 6 , t in [0,41)
__global__ void __launch_bounds__(256) k_tconv(const float* __restrict__ res,
        const float* __restrict__ wcT, const float* __restrict__ bsum,
        float* __restrict__ out) {
    int n0 = blockIdx.x * 64;
    int bt = blockIdx.y;
    int b = bt / TREC, t = bt % TREC;
    __shared__ float As[64][68];
    __shared__ float Bs[64][68];
    int tid = threadIdx.x;
    int tx = tid & 15, ty = tid >> 4;
    float acc[4][4] = {};
    for (int dt = 0; dt < 11; dt++) {
        int ts = t + dt - 5;
        if (ts < 0 || ts >= TREC) continue;   // uniform across block
        loadA_T(As, &res[(((size_t)b * FREQ + ts) * NN + n0) * 64], 64, tid);
        loadB_D(Bs, &wcT[(size_t)dt * 64 * 64], 64, tid);
        __syncthreads();
        mm64(As, Bs, acc, tx, ty);
        __syncthreads();
    }
    const float inv6 = 1.f / 6.f;
#pragma unroll
    for (int i = 0; i < 4; i++) {
        int m = ty * 4 + i;
#pragma unroll
        for (int j = 0; j < 4; j++) {
            int d = tx * 4 + j;
            out[(((size_t)bt) * NN + n0 + m) * 64 + d] = (acc[i][j] + bsum[d]) * inv6;
        }
    }
}

// ================= mixprop propagation step =================
// hout = ALPHA*xin + (1-ALPHA) * A @ hin, per bt slice (1024x64)
__global__ void __launch_bounds__(256) k_prop(const float* __restrict__ A,
        const float* __restrict__ hin, const float* __restrict__ xin,
        float* __restrict__ hout) {
    int m0 = blockIdx.x * 64;
    size_t base = (size_t)blockIdx.y * (NN * 64);
    __shared__ float As[64][68];
    __shared__ float Bs[64][68];
    int tid = threadIdx.x;
    int tx = tid & 15, ty = tid >> 4;
    float acc[4][4] = {};
    for (int k0 = 0; k0 < NN; k0 += 64) {
        loadA_T(As, &A[(size_t)m0 * NN + k0], NN, tid);
        loadB_D(Bs, &hin[base + (size_t)k0 * 64], 64, tid);
        __syncthreads();
        mm64(As, Bs, acc, tx, ty);
        __syncthreads();
    }
#pragma unroll
    for (int i = 0; i < 4; i++) {
        int v = m0 + ty * 4 + i;
#pragma unroll
        for (int j = 0; j < 4; j++) {
            int d = tx * 4 + j;
            size_t idx = base + (size_t)v * 64 + d;
            hout[idx] = ALPHA * xin[idx] + (1.f - ALPHA) * acc[i][j];
        }
    }
}

// ================= mixprop combine + residual =================
// out = [x,h1a,h2a]@g1w + g1b + [x,h1b,h2b]@g2w + g2b + resid
__global__ void __launch_bounds__(256) k_combine(const float* __restrict__ x,
        const float* __restrict__ h1a, const float* __restrict__ h2a,
        const float* __restrict__ h1b, const float* __restrict__ h2b,
        const float* __restrict__ g1w, const float* __restrict__ g1b,
        const float* __restrict__ g2w, const float* __restrict__ g2b,
        const float* __restrict__ resid, float* __restrict__ out,
        int rdiv, int rmul, int roff,
        int odiv, int omul, int ooff) {
    int n0 = blockIdx.x * 64;
    int bt = blockIdx.y;
    size_t base = (size_t)bt * (NN * 64);
    const float* srcs[6] = {x, h1a, h2a, x, h1b, h2b};
    const float* wgt[6]  = {g1w, g1w + 4096, g1w + 8192, g2w, g2w + 4096, g2w + 8192};
    __shared__ float As[64][68];
    __shared__ float Bs[64][68];
    int tid = threadIdx.x;
    int tx = tid & 15, ty = tid >> 4;
    float acc[4][4] = {};
    for (int p = 0; p < 6; p++) {
        loadA_T(As, &srcs[p][base + (size_t)n0 * 64], 64, tid);
        loadB_D(Bs, wgt[p], 64, tid);
        __syncthreads();
        mm64(As, Bs, acc, tx, ty);
        __syncthreads();
    }
    int rrow = (bt / rdiv) * rmul + (bt % rdiv) + roff;
    int orow = (bt / odiv) * omul + (bt % odiv) + ooff;
#pragma unroll
    for (int i = 0; i < 4; i++) {
        int m = n0 + ty * 4 + i;
#pragma unroll
        for (int j = 0; j < 4; j++) {
            int d = tx * 4 + j;
            float r = resid[((size_t)rrow * NN + m) * 64 + d];
            out[((size_t)orow * NN + m) * 64 + d] = acc[i][j] + g1b[d] + g2b[d] + r;
        }
    }
}

// ================= AR: last-timestep t_inception =================
// out[b,n,o] = (bsum + sum_{j=0}^{5} Wc[j] @ cur[b, s+5+j, n, :]) / 6
__global__ void __launch_bounds__(256) k_tcl(const float* __restrict__ cur,
        const float* __restrict__ wcT, const float* __restrict__ bsum,
        float* __restrict__ out, int s) {
    int row0 = blockIdx.x * 64;      // over 8*1024 rows
    int b = row0 >> 10;
    int n0 = row0 & 1023;
    __shared__ float As[64][68];
    __shared__ float Bs[64][68];
    int tid = threadIdx.x;
    int tx = tid & 15, ty = tid >> 4;
    float acc[4][4] = {};
    for (int j = 0; j < 6; j++) {
        loadA_T(As, &cur[(((size_t)b * 23 + s + 5 + j) * NN + n0) * 64], 64, tid);
        loadB_D(Bs, &wcT[(size_t)j * 64 * 64], 64, tid);
        __syncthreads();
        mm64(As, Bs, acc, tx, ty);
        __syncthreads();
    }
    const float inv6 = 1.f / 6.f;
#pragma unroll
    for (int i = 0; i < 4; i++) {
        int m = row0 + ty * 4 + i;
#pragma unroll
        for (int j = 0; j < 4; j++) {
            int d = tx * 4 + j;
            out[(size_t)m * 64 + d] = (acc[i][j] + bsum[d]) * inv6;
        }
    }
}

// ================= AR cur-buffer init: cur[:,0:11] = res[:,31:42] =================
__global__ void k_cur_init(const float* __restrict__ res, float* __restrict__ cur) {
    size_t total = (size_t)NB * MAXK * NN * 64;
    for (size_t idx = (size_t)blockIdx.x * blockDim.x + threadIdx.x; idx < total;
         idx += (size_t)gridDim.x * blockDim.x) {
        int d = idx & 63;
        int n = (idx >> 6) & 1023;
        int j = (int)((idx >> 16) % MAXK);
        int b = (int)(idx / ((size_t)MAXK << 16));
        cur[(((size_t)b * 23 + j) * NN + n) * 64 + d] =
            res[(((size_t)b * FREQ + 31 + j) * NN + n) * 64 + d];
    }
}

// ================= decoder MLP for rec =================
__global__ void __launch_bounds__(256) k_dec_rec(const float* __restrict__ res,
        const float* __restrict__ stout,
        const float* __restrict__ w1, const float* __restrict__ b1,
        const float* __restrict__ w2, const float* __restrict__ b2,
        float* __restrict__ out) {
    int n0 = blockIdx.x * 64;
    int f  = blockIdx.y;
    int b  = blockIdx.z;
    const float* src = (f == 0)
        ? &res[(((size_t)b * FREQ) * NN + n0) * 64]
        : &stout[(((size_t)b * TREC + f - 1) * NN + n0) * 64];
    __shared__ float hs[64][129];
    int tid = threadIdx.x;
    {
        int r = tid >> 2;
        int j0 = (tid & 3) * 32;
        const float* xr = &src[(size_t)r * 64];
        for (int j = j0; j < j0 + 32; j++) {
            float h = b1[j];
#pragma unroll
            for (int c = 0; c < 64; c++) h = fmaf(xr[c], w1[c * 128 + j], h);
            hs[r][j] = fmaxf(h, 0.f);
        }
    }
    __syncthreads();
    for (int o = tid; o < 512; o += 256) {
        int r = o & 63, s = o >> 6;
        float acc = b2[s];
#pragma unroll
        for (int j = 0; j < 128; j++) acc = fmaf(hs[r][j], w2[j * 8 + s], acc);
        out[((size_t)b * NT + f * SEG + s) * NN + n0 + r] = acc;
    }
}

// ================= decoder MLP for pred (with the reference's direct reshape) =================
// pred flat per batch: t*8192 + n*8 + s
__global__ void __launch_bounds__(256) k_dec_pred(const float* __restrict__ cur,
        const float* __restrict__ w1, const float* __restrict__ b1,
        const float* __restrict__ w2, const float* __restrict__ b2,
        float* __restrict__ out) {
    int n0 = blockIdx.x * 64;
    int t  = blockIdx.y;
    int b  = blockIdx.z;
    const float* src = &cur[(((size_t)b * 23 + MAXK + t) * NN + n0) * 64];
    __shared__ float hs[64][129];
    int tid = threadIdx.x;
    {
        int r = tid >> 2;
        int j0 = (tid & 3) * 32;
        const float* xr = &src[(size_t)r * 64];
        for (int j = j0; j < j0 + 32; j++) {
            float h = b1[j];
#pragma unroll
            for (int c = 0; c < 64; c++) h = fmaf(xr[c], w1[c * 128 + j], h);
            hs[r][j] = fmaxf(h, 0.f);
        }
    }
    __syncthreads();
    for (int o = tid; o < 512; o += 256) {
        int r = o >> 3, s = o & 7;
        float acc = b2[s];
#pragma unroll
        for (int j = 0; j < 128; j++) acc = fmaf(hs[r][j], w2[j * 8 + s], acc);
        out[(size_t)b * (NSTEP * SEG * NN) + (size_t)t * 8192 + (size_t)(n0 + r) * 8 + s] = acc;
    }
}

// ================= host launcher =================
extern "C" void kernel_launch(void* const* d_in, const int* in_sizes, int n_in,
                              void* d_out, int out_size) {
    (void)in_sizes; (void)n_in; (void)out_size;
    const float* x_diff = (const float*)d_in[0];
    const float* adj    = (const float*)d_in[1];
    const float* enc_w1 = (const float*)d_in[2];
    const float* enc_b1 = (const float*)d_in[3];
    const float* enc_w2 = (const float*)d_in[4];
    const float* enc_b2 = (const float*)d_in[5];
    const float* dec_w1 = (const float*)d_in[6];
    const float* dec_b1 = (const float*)d_in[7];
    const float* dec_w2 = (const float*)d_in[8];
    const float* dec_b2 = (const float*)d_in[9];
    const float* g1_w   = (const float*)d_in[10];
    const float* g1_b   = (const float*)d_in[11];
    const float* g2_w   = (const float*)d_in[12];
    const float* g2_b   = (const float*)d_in[13];
    const float* cw[6], *cb[6];
    for (int i = 0; i < 6; i++) {
        cw[i] = (const float*)d_in[14 + 2 * i];
        cb[i] = (const float*)d_in[15 + 2 * i];
    }

    float* scratch = nullptr;
    cudaGetSymbolAddress((void**)&scratch, g_scratch);
    float* a1    = scratch + OFF_A1;
    float* a2    = scratch + OFF_A2;
    float* wcT   = scratch + OFF_WCT;
    float* bsum  = scratch + OFF_BSUM;
    float* res   = scratch + OFF_RES;
    float* conv  = scratch + OFF_CONV;
    float* h1a   = scratch + OFF_H1A;
    float* h2a   = scratch + OFF_H2A;
    float* h1b   = scratch + OFF_H1B;
    float* h2b   = scratch + OFF_H2B;
    float* stout = scratch + OFF_STOUT;
    float* cur   = scratch + OFF_CUR;
    float* tcl   = scratch + OFF_TCL;
    float* ph1a  = scratch + OFF_PH1A;
    float* ph1b  = scratch + OFF_PH1B;
    float* ph2a  = scratch + OFF_PH2A;
    float* ph2b  = scratch + OFF_PH2B;

    float* rec_out  = (float*)d_out;
    float* pred_out = rec_out + (size_t)NB * NT * NN;

    // ---- preprocessing ----
    k_norm_adj<<<NN, 256>>>(adj, a1, a2);
    k_comb_w<<<(11 * 64 * 64 + 255) / 256, 256>>>(cw[0], cw[1], cw[2], cw[3], cw[4], cw[5],
                                                  cb[0], cb[1], cb[2], cb[3], cb[4], cb[5],
                                                  wcT, bsum);
    // ---- encoder ----
    k_enc<<<dim3(16, FREQ, NB), 256>>>(x_diff, enc_w1, enc_b1, enc_w2, enc_b2, res);

    // ---- rec-path stconv ----
    dim3 gRec(16, NB * TREC);
    k_tconv<<<gRec, 256>>>(res, wcT, bsum, conv);
    k_prop<<<gRec, 256>>>(a1, conv, conv, h1a);
    k_prop<<<gRec, 256>>>(a2, conv, conv, h1b);
    k_prop<<<gRec, 256>>>(a1, h1a, conv, h2a);
    k_prop<<<gRec, 256>>>(a2, h1b, conv, h2b);
    k_combine<<<gRec, 256>>>(conv, h1a, h2a, h1b, h2b, g1_w, g1_b, g2_w, g2_b,
                             res, stout,
                             TREC, FREQ, 0,     // resid row = b*42 + t
                             TREC, TREC, 0);    // out   row = bt
    // ---- rec decoder ----
    k_dec_rec<<<dim3(16, FREQ, NB), 256>>>(res, stout, dec_w1, dec_b1, dec_w2, dec_b2, rec_out);

    // ---- autoregressive loop ----
    k_cur_init<<<4096, 256>>>(res, cur);
    dim3 gAR(16, NB);
    for (int s = 0; s < NSTEP; s++) {
        k_tcl<<<128, 256>>>(cur, wcT, bsum, tcl, s);
        k_prop<<<gAR, 256>>>(a1, tcl, tcl, ph1a);
        k_prop<<<gAR, 256>>>(a2, tcl, tcl, ph1b);
        k_prop<<<gAR, 256>>>(a1, ph1a, tcl, ph2a);
        k_prop<<<gAR, 256>>>(a2, ph1b, tcl, ph2b);
        k_combine<<<gAR, 256>>>(tcl, ph1a, ph2a, ph1b, ph2b, g1_w, g1_b, g2_w, g2_b,
                                cur, cur,
                                1, 23, s + 10,   // resid row = b*23 + s+10
                                1, 23, s + 11);  // out   row = b*23 + s+11
    }
    // ---- pred decoder ----
    k_dec_pred<<<dim3(16, NSTEP, NB), 256>>>(cur, dec_w1, dec_b1, dec_w2, dec_b2, pred_out);
}

// round 4
// speedup vs baseline: 1.2251x; 1.2251x over previous
#include <cuda_runtime.h>
#include <cstdint>

// ---------------- problem constants ----------------
#define NB   8
#define NT   336
#define NN   1024
#define FREQ 42
#define SEG  8
#define TREC 41
#define NSTEP 12
#define MAXK 11
#define ALPHA 0.05f
#define BETA  0.95f

// ---------------- scratch layout (floats) ----------------
static const size_t OFF_A1   = 0;                         // 1024*1024
static const size_t OFF_A2   = OFF_A1   + 1048576;
static const size_t OFF_WCT  = OFF_A2   + 1048576;        // 11*64*64
static const size_t OFF_BSUM = OFF_WCT  + 45056;          // 64
static const size_t OFF_EC   = OFF_BSUM + 64;             // 5*64*64
static const size_t OFF_EB   = OFF_EC   + 20480;          // 64
static const size_t OFF_RES  = OFF_EB   + 64;             // 8*42*1024*64
static const size_t OFF_CONV = OFF_RES  + 22020096;       // 8*41*1024*64
static const size_t OFF_H1A  = OFF_CONV + 21495808;
static const size_t OFF_H2A  = OFF_H1A  + 21495808;
static const size_t OFF_H1B  = OFF_H2A  + 21495808;
static const size_t OFF_H2B  = OFF_H1B  + 21495808;
static const size_t OFF_STOUT= OFF_H2B  + 21495808;
static const size_t OFF_CUR  = OFF_STOUT+ 21495808;       // 8*23*1024*64
static const size_t OFF_TCL  = OFF_CUR  + 12058624;       // 8*1024*64
static const size_t OFF_PH1A = OFF_TCL  + 524288;
static const size_t OFF_PH1B = OFF_PH1A + 524288;
static const size_t OFF_PH2A = OFF_PH1B + 524288;
static const size_t OFF_PH2B = OFF_PH2A + 524288;
static const size_t OFF_PART = OFF_PH2B + 524288;         // 8 slots * 8*1024*64
static const size_t SCRATCH_TOTAL = OFF_PART + 4194304;

__device__ float g_scratch[SCRATCH_TOTAL];

// =====================================================================
// GEMM64 chunk macro: accumulates C[128 x 64] += Asrc[128 x 64] @ Bsrc[64 x 64]
// Asrc: 128 rows (ld=64, k contiguous). Bsrc: k-major [k][n], ld=64.
// Needs in scope: __shared__ float As[16][132], Bs[16][68];
//                 int tid, tx (tid&15), ty (tid>>4); float acc[8][4].
// Microtile rows: {ty*4+i, 64+ty*4+i}, cols: tx*4+j.
// =====================================================================
#define GEMM64_CHUNK(ASRC, BSRC) do {                                          \
    const float* _as = (ASRC); const float* _bs = (BSRC);                      \
    for (int k0 = 0; k0 < 64; k0 += 16) {                                      \
        _Pragma("unroll")                                                      \
        for (int i = 0; i < 2; i++) {                                          \
            int li = tid + i * 256;                                            \
            int m = li & 127, k4 = li >> 7;                                    \
            float4 v = *(const float4*)&_as[(size_t)m * 64 + k0 + k4 * 4];     \
            As[k4*4+0][m] = v.x; As[k4*4+1][m] = v.y;                          \
            As[k4*4+2][m] = v.z; As[k4*4+3][m] = v.w;                          \
        }                                                                      \
        {                                                                      \
            int kk = tid >> 4, n4 = (tid & 15) * 4;                            \
            *(float4*)&Bs[kk][n4] =                                            \
                *(const float4*)&_bs[(size_t)(k0 + kk) * 64 + n4];             \
        }                                                                      \
        __syncthreads();                                                       \
        _Pragma("unroll")                                                      \
        for (int k = 0; k < 16; k++) {                                         \
            float a_[8], b_[4];                                                \
            *(float4*)&a_[0] = *(const float4*)&As[k][ty * 4];                 \
            *(float4*)&a_[4] = *(const float4*)&As[k][64 + ty * 4];            \
            *(float4*)&b_[0] = *(const float4*)&Bs[k][tx * 4];                 \
            _Pragma("unroll")                                                  \
            for (int i = 0; i < 8; i++) {                                      \
                _Pragma("unroll")                                              \
                for (int j = 0; j < 4; j++)                                    \
                    acc[i][j] = fmaf(a_[i], b_[j], acc[i][j]);                 \
            }                                                                  \
        }                                                                      \
        __syncthreads();                                                       \
    }                                                                          \
} while (0)

// ================= adjacency normalization =================
__global__ void k_norm_adj(const float* __restrict__ adj,
                           float* __restrict__ a1, float* __restrict__ a2) {
    int v = blockIdx.x;
    int tid = threadIdx.x;
    __shared__ float r1[256], r2[256];
    float s1 = 0.f, s2 = 0.f;
    for (int n = tid; n < NN; n += 256) {
        s1 += adj[(size_t)v * NN + n];
        s2 += adj[(size_t)n * NN + v];
    }
    r1[tid] = s1; r2[tid] = s2;
    __syncthreads();
    for (int off = 128; off > 0; off >>= 1) {
        if (tid < off) { r1[tid] += r1[tid + off]; r2[tid] += r2[tid + off]; }
        __syncthreads();
    }
    float inv1 = 1.f / (r1[0] + 1.f);
    float inv2 = 1.f / (r2[0] + 1.f);
    for (int n = tid; n < NN; n += 256) {
        float d = (n == v) ? 1.f : 0.f;
        a1[(size_t)v * NN + n] = (adj[(size_t)v * NN + n] + d) * inv1;
        a2[(size_t)v * NN + n] = (adj[(size_t)n * NN + v] + d) * inv2;
    }
}

// ================= combine conv weights =================
__global__ void k_comb_w(const float* w0, const float* w1, const float* w2,
                         const float* w3, const float* w4, const float* w5,
                         const float* cb0, const float* cb1, const float* cb2,
                         const float* cb3, const float* cb4, const float* cb5,
                         float* __restrict__ wcT, float* __restrict__ bsum) {
    int idx = blockIdx.x * 256 + threadIdx.x;
    if (idx >= 11 * 64 * 64) return;
    int o = idx & 63;
    int c = (idx >> 6) & 63;
    int dt = idx >> 12;
    int dv = dt - 5;
    int ad = dv < 0 ? -dv : dv;
    const float* ws[6] = {w0, w1, w2, w3, w4, w5};
    float acc = 0.f;
    for (int i = ad; i < 6; i++) {
        int K = 2 * i + 1;
        acc += ws[i][(size_t)(o * 64 + c) * K + (dv + i)];
    }
    wcT[((size_t)dt * 64 + c) * 64 + o] = acc;
    if (dt == 0 && c == 0)
        bsum[o] = cb0[o] + cb1[o] + cb2[o] + cb3[o] + cb4[o] + cb5[o];
}

// ================= combine mixprop weights =================
// term0 = (G10+aG11+aG12)+(G20+aG21+aG22); term1 = bG11+abG12; term2 = b^2 G12
// term3 = bG21+abG22; term4 = b^2 G22. ec layout [term][c][o] (k-major).
__global__ void k_comb_g(const float* __restrict__ g1w, const float* __restrict__ g1b,
                         const float* __restrict__ g2w, const float* __restrict__ g2b,
                         float* __restrict__ ec, float* __restrict__ eb) {
    int idx = blockIdx.x * 256 + threadIdx.x;
    if (idx >= 5 * 4096) return;
    int term = idx >> 12;
    int co = idx & 4095;    // c*64+o
    float v;
    if (term == 0) {
        v = g1w[co] + ALPHA * (g1w[4096 + co] + g1w[8192 + co])
          + g2w[co] + ALPHA * (g2w[4096 + co] + g2w[8192 + co]);
    } else if (term == 1) {
        v = BETA * g1w[4096 + co] + ALPHA * BETA * g1w[8192 + co];
    } else if (term == 2) {
        v = BETA * BETA * g1w[8192 + co];
    } else if (term == 3) {
        v = BETA * g2w[4096 + co] + ALPHA * BETA * g2w[8192 + co];
    } else {
        v = BETA * BETA * g2w[8192 + co];
    }
    ec[idx] = v;
    if (idx < 64) eb[idx] = g1b[idx] + g2b[idx];
}

// ================= encoder MLP =================
__global__ void __launch_bounds__(256) k_enc(const float* __restrict__ x,
        const float* __restrict__ w1, const float* __restrict__ b1,
        const float* __restrict__ w2, const float* __restrict__ b2,
        float* __restrict__ out) {
    int n0 = blockIdx.x * 64;
    int f  = blockIdx.y;
    int b  = blockIdx.z;
    __shared__ float xs[64][8];
    __shared__ float hs[64][129];
    __shared__ float w1s[8 * 128];
    int tid = threadIdx.x;
    for (int i = tid; i < 1024; i += 256) w1s[i] = w1[i];
    for (int i = tid; i < 512; i += 256) {
        int s = i >> 6, r = i & 63;
        xs[r][s] = x[((size_t)(b * NT) + f * SEG + s) * NN + n0 + r];
    }
    __syncthreads();
    {
        int r = tid >> 2;
        int j0 = (tid & 3) * 32;
        float xv[8];
#pragma unroll
        for (int s = 0; s < 8; s++) xv[s] = xs[r][s];
        for (int j = j0; j < j0 + 32; j++) {
            float h = b1[j];
#pragma unroll
            for (int s = 0; s < 8; s++) h = fmaf(xv[s], w1s[s * 128 + j], h);
            hs[r][j] = fmaxf(h, 0.f);
        }
    }
    __syncthreads();
    {
        int r = tid >> 2;
        int d0 = (tid & 3) * 16;
        for (int d = d0; d < d0 + 16; d++) {
            float acc = b2[d];
#pragma unroll
            for (int j = 0; j < 128; j++) acc = fmaf(hs[r][j], w2[j * 64 + d], acc);
            out[(((size_t)b * FREQ + f) * NN + n0 + r) * 64 + d] = acc;
        }
    }
}

// ================= t_inception (rec path), 128x64 tiles =================
__global__ void __launch_bounds__(256) k_tconv(const float* __restrict__ res,
        const float* __restrict__ wcT, const float* __restrict__ bsum,
        float* __restrict__ out) {
    int m0 = blockIdx.x * 128;
    int bt = blockIdx.y;
    int b = bt / TREC, t = bt % TREC;
    __shared__ float As[16][132];
    __shared__ float Bs[16][68];
    int tid = threadIdx.x;
    int tx = tid & 15, ty = tid >> 4;
    float acc[8][4] = {};
    for (int dt = 0; dt < MAXK; dt++) {
        int ts = t + dt - 5;
        if (ts < 0 || ts >= TREC) continue;
        GEMM64_CHUNK(&res[(((size_t)b * FREQ + ts) * NN + m0) * 64],
                     &wcT[(size_t)dt * 4096]);
    }
    const float inv6 = 1.f / 6.f;
    float4 bsv = *(const float4*)&bsum[tx * 4];
    float bsa[4] = {bsv.x, bsv.y, bsv.z, bsv.w};
#pragma unroll
    for (int i = 0; i < 8; i++) {
        int m = m0 + (i < 4 ? ty * 4 + i : 60 + ty * 4 + i);
        float4 v;
        v.x = (acc[i][0] + bsa[0]) * inv6;
        v.y = (acc[i][1] + bsa[1]) * inv6;
        v.z = (acc[i][2] + bsa[2]) * inv6;
        v.w = (acc[i][3] + bsa[3]) * inv6;
        *(float4*)&out[((size_t)bt * NN + m) * 64 + tx * 4] = v;
    }
}

// ================= rec prop: raw A@h, 128x128 tiles, bt-paired, dir in z =====
__global__ void __launch_bounds__(256) k_prop128(
        const float* __restrict__ a1, const float* __restrict__ a2,
        const float* __restrict__ hin0, const float* __restrict__ hin1,
        float* __restrict__ hout0, float* __restrict__ hout1) {
    const float* A    = blockIdx.z ? a2 : a1;
    const float* hin  = blockIdx.z ? hin1 : hin0;
    float*       hout = blockIdx.z ? hout1 : hout0;
    int m0 = blockIdx.x * 128;
    size_t base0 = (size_t)(2 * blockIdx.y) * (NN * 64);
    size_t base1 = base0 + (size_t)NN * 64;
    __shared__ float As[16][132];
    __shared__ float Bs[16][132];
    int tid = threadIdx.x;
    int tx = tid & 15, ty = tid >> 4;
    float acc[8][8] = {};
    for (int k0 = 0; k0 < NN; k0 += 16) {
#pragma unroll
        for (int i = 0; i < 2; i++) {
            int li = tid + i * 256;
            int m = li & 127, k4 = li >> 7;
            float4 v = *(const float4*)&A[(size_t)(m0 + m) * NN + k0 + k4 * 4];
            As[k4*4+0][m] = v.x; As[k4*4+1][m] = v.y;
            As[k4*4+2][m] = v.z; As[k4*4+3][m] = v.w;
        }
#pragma unroll
        for (int i = 0; i < 2; i++) {
            int li = tid + i * 256;
            int kk = li >> 5;
            int n4 = (li & 31) * 4;
            size_t src = (n4 < 64) ? base0 + (size_t)(k0 + kk) * 64 + n4
                                   : base1 + (size_t)(k0 + kk) * 64 + (n4 - 64);
            *(float4*)&Bs[kk][n4] = *(const float4*)&hin[src];
        }
        __syncthreads();
#pragma unroll
        for (int k = 0; k < 16; k++) {
            float a_[8], b_[8];
            *(float4*)&a_[0] = *(const float4*)&As[k][ty * 4];
            *(float4*)&a_[4] = *(const float4*)&As[k][64 + ty * 4];
            *(float4*)&b_[0] = *(const float4*)&Bs[k][tx * 4];
            *(float4*)&b_[4] = *(const float4*)&Bs[k][64 + tx * 4];
#pragma unroll
            for (int i = 0; i < 8; i++)
#pragma unroll
                for (int j = 0; j < 8; j++)
                    acc[i][j] = fmaf(a_[i], b_[j], acc[i][j]);
        }
        __syncthreads();
    }
    float* o0 = hout + base0 + (size_t)m0 * 64;
    float* o1 = hout + base1 + (size_t)m0 * 64;
#pragma unroll
    for (int i = 0; i < 8; i++) {
        int m = (i < 4 ? ty * 4 + i : 60 + ty * 4 + i);
        float4 v0 = make_float4(acc[i][0], acc[i][1], acc[i][2], acc[i][3]);
        float4 v1 = make_float4(acc[i][4], acc[i][5], acc[i][6], acc[i][7]);
        *(float4*)&o0[(size_t)m * 64 + tx * 4] = v0;
        *(float4*)&o1[(size_t)m * 64 + tx * 4] = v1;
    }
}

// ================= AR prop with split-K=4, b-paired, (dir,chunk) in z ========
__global__ void __launch_bounds__(256) k_prop_sk(
        const float* __restrict__ a1, const float* __restrict__ a2,
        const float* __restrict__ hin0, const float* __restrict__ hin1,
        float* __restrict__ part) {
    int dir = blockIdx.z >> 2;
    int chunk = blockIdx.z & 3;
    const float* A   = dir ? a2 : a1;
    const float* hin = dir ? hin1 : hin0;
    int m0 = blockIdx.x * 128;
    int b0 = 2 * blockIdx.y, b1 = b0 + 1;
    size_t base0 = (size_t)b0 * (NN * 64);
    size_t base1 = (size_t)b1 * (NN * 64);
    __shared__ float As[16][132];
    __shared__ float Bs[16][132];
    int tid = threadIdx.x;
    int tx = tid & 15, ty = tid >> 4;
    float acc[8][8] = {};
    int kend = chunk * 256 + 256;
    for (int k0 = chunk * 256; k0 < kend; k0 += 16) {
#pragma unroll
        for (int i = 0; i < 2; i++) {
            int li = tid + i * 256;
            int m = li & 127, k4 = li >> 7;
            float4 v = *(const float4*)&A[(size_t)(m0 + m) * NN + k0 + k4 * 4];
            As[k4*4+0][m] = v.x; As[k4*4+1][m] = v.y;
            As[k4*4+2][m] = v.z; As[k4*4+3][m] = v.w;
        }
#pragma unroll
        for (int i = 0; i < 2; i++) {
            int li = tid + i * 256;
            int kk = li >> 5;
            int n4 = (li & 31) * 4;
            size_t src = (n4 < 64) ? base0 + (size_t)(k0 + kk) * 64 + n4
                                   : base1 + (size_t)(k0 + kk) * 64 + (n4 - 64);
            *(float4*)&Bs[kk][n4] = *(const float4*)&hin[src];
        }
        __syncthreads();
#pragma unroll
        for (int k = 0; k < 16; k++) {
            float a_[8], b_[8];
            *(float4*)&a_[0] = *(const float4*)&As[k][ty * 4];
            *(float4*)&a_[4] = *(const float4*)&As[k][64 + ty * 4];
            *(float4*)&b_[0] = *(const float4*)&Bs[k][tx * 4];
            *(float4*)&b_[4] = *(const float4*)&Bs[k][64 + tx * 4];
#pragma unroll
            for (int i = 0; i < 8; i++)
#pragma unroll
                for (int j = 0; j < 8; j++)
                    acc[i][j] = fmaf(a_[i], b_[j], acc[i][j]);
        }
        __syncthreads();
    }
    int slot = (dir * 4 + chunk) * NB;
    float* o0 = part + ((size_t)(slot + b0)) * (NN * 64) + (size_t)m0 * 64;
    float* o1 = part + ((size_t)(slot + b1)) * (NN * 64) + (size_t)m0 * 64;
#pragma unroll
    for (int i = 0; i < 8; i++) {
        int m = (i < 4 ? ty * 4 + i : 60 + ty * 4 + i);
        float4 v0 = make_float4(acc[i][0], acc[i][1], acc[i][2], acc[i][3]);
        float4 v1 = make_float4(acc[i][4], acc[i][5], acc[i][6], acc[i][7]);
        *(float4*)&o0[(size_t)m * 64 + tx * 4] = v0;
        *(float4*)&o1[(size_t)m * 64 + tx * 4] = v1;
    }
}

// ================= split-K reduce: sums 4 chunks per dir =================
__global__ void k_reduce4(const float* __restrict__ part,
                          float* __restrict__ o0, float* __restrict__ o1) {
    const size_t S = (size_t)NB * NN * 64;   // 524288 per slot
    size_t i = ((size_t)blockIdx.x * blockDim.x + threadIdx.x) * 4;
    if (i >= S) return;
    float4 a = *(const float4*)&part[i];
    float4 b = *(const float4*)&part[S + i];
    float4 c = *(const float4*)&part[2 * S + i];
    float4 d = *(const float4*)&part[3 * S + i];
    float4 r = make_float4(a.x + b.x + c.x + d.x, a.y + b.y + c.y + d.y,
                           a.z + b.z + c.z + d.z, a.w + b.w + c.w + d.w);
    *(float4*)&o0[i] = r;
    a = *(const float4*)&part[4 * S + i];
    b = *(const float4*)&part[5 * S + i];
    c = *(const float4*)&part[6 * S + i];
    d = *(const float4*)&part[7 * S + i];
    r = make_float4(a.x + b.x + c.x + d.x, a.y + b.y + c.y + d.y,
                    a.z + b.z + c.z + d.z, a.w + b.w + c.w + d.w);
    *(float4*)&o1[i] = r;
}

// ================= combine (5-term) + bias + residual =================
__global__ void __launch_bounds__(256) k_combine(const float* __restrict__ x,
        const float* __restrict__ s1, const float* __restrict__ s2,
        const float* __restrict__ t1, const float* __restrict__ t2,
        const float* __restrict__ ec, const float* __restrict__ eb,
        const float* __restrict__ resid, float* __restrict__ out,
        int rdiv, int rmul, int roff,
        int odiv, int omul, int ooff) {
    int m0 = blockIdx.x * 128;
    int bt = blockIdx.y;
    size_t base = (size_t)bt * (NN * 64) + (size_t)m0 * 64;
    __shared__ float As[16][132];
    __shared__ float Bs[16][68];
    int tid = threadIdx.x;
    int tx = tid & 15, ty = tid >> 4;
    float acc[8][4] = {};
    GEMM64_CHUNK(x  + base, ec);
    GEMM64_CHUNK(s1 + base, ec + 4096);
    GEMM64_CHUNK(s2 + base, ec + 8192);
    GEMM64_CHUNK(t1 + base, ec + 12288);
    GEMM64_CHUNK(t2 + base, ec + 16384);
    int rrow = (bt / rdiv) * rmul + (bt % rdiv) + roff;
    int orow = (bt / odiv) * omul + (bt % odiv) + ooff;
    float4 ebv = *(const float4*)&eb[tx * 4];
    float eba[4] = {ebv.x, ebv.y, ebv.z, ebv.w};
#pragma unroll
    for (int i = 0; i < 8; i++) {
        int m = m0 + (i < 4 ? ty * 4 + i : 60 + ty * 4 + i);
        float4 rv = *(const float4*)&resid[((size_t)rrow * NN + m) * 64 + tx * 4];
        float4 v;
        v.x = acc[i][0] + eba[0] + rv.x;
        v.y = acc[i][1] + eba[1] + rv.y;
        v.z = acc[i][2] + eba[2] + rv.z;
        v.w = acc[i][3] + eba[3] + rv.w;
        *(float4*)&out[((size_t)orow * NN + m) * 64 + tx * 4] = v;
    }
}

// ================= AR last-timestep inception, 128x64 tiles =================
__global__ void __launch_bounds__(256) k_tcl(const float* __restrict__ cur,
        const float* __restrict__ wcT, const float* __restrict__ bsum,
        float* __restrict__ out, int s) {
    int gm = blockIdx.x;           // 0..63
    int b  = gm >> 3;
    int m0 = (gm & 7) * 128;
    __shared__ float As[16][132];
    __shared__ float Bs[16][68];
    int tid = threadIdx.x;
    int tx = tid & 15, ty = tid >> 4;
    float acc[8][4] = {};
    for (int j = 0; j < 6; j++) {
        GEMM64_CHUNK(&cur[(((size_t)b * 23 + s + 5 + j) * NN + m0) * 64],
                     &wcT[(size_t)j * 4096]);
    }
    const float inv6 = 1.f / 6.f;
    float4 bsv = *(const float4*)&bsum[tx * 4];
    float bsa[4] = {bsv.x, bsv.y, bsv.z, bsv.w};
#pragma unroll
    for (int i = 0; i < 8; i++) {
        int m = m0 + (i < 4 ? ty * 4 + i : 60 + ty * 4 + i);
        float4 v;
        v.x = (acc[i][0] + bsa[0]) * inv6;
        v.y = (acc[i][1] + bsa[1]) * inv6;
        v.z = (acc[i][2] + bsa[2]) * inv6;
        v.w = (acc[i][3] + bsa[3]) * inv6;
        *(float4*)&out[((size_t)b * NN + m) * 64 + tx * 4] = v;
    }
}

// ================= AR cur-buffer init =================
__global__ void k_cur_init(const float* __restrict__ res, float* __restrict__ cur) {
    size_t total = (size_t)NB * MAXK * NN * 64;
    for (size_t idx = (size_t)blockIdx.x * blockDim.x + threadIdx.x; idx < total;
         idx += (size_t)gridDim.x * blockDim.x) {
        int d = idx & 63;
        int n = (idx >> 6) & 1023;
        int j = (int)((idx >> 16) % MAXK);
        int b = (int)(idx / ((size_t)MAXK << 16));
        cur[(((size_t)b * 23 + j) * NN + n) * 64 + d] =
            res[(((size_t)b * FREQ + 31 + j) * NN + n) * 64 + d];
    }
}

// ================= decoder MLP for rec =================
__global__ void __launch_bounds__(256) k_dec_rec(const float* __restrict__ res,
        const float* __restrict__ stout,
        const float* __restrict__ w1, const float* __restrict__ b1,
        const float* __restrict__ w2, const float* __restrict__ b2,
        float* __restrict__ out) {
    int n0 = blockIdx.x * 64;
    int f  = blockIdx.y;
    int b  = blockIdx.z;
    const float* src = (f == 0)
        ? &res[(((size_t)b * FREQ) * NN + n0) * 64]
        : &stout[(((size_t)b * TREC + f - 1) * NN + n0) * 64];
    __shared__ float hs[64][129];
    int tid = threadIdx.x;
    {
        int r = tid >> 2;
        int j0 = (tid & 3) * 32;
        const float* xr = &src[(size_t)r * 64];
        for (int j = j0; j < j0 + 32; j++) {
            float h = b1[j];
#pragma unroll
            for (int c = 0; c < 64; c++) h = fmaf(xr[c], w1[c * 128 + j], h);
            hs[r][j] = fmaxf(h, 0.f);
        }
    }
    __syncthreads();
    for (int o = tid; o < 512; o += 256) {
        int r = o & 63, s = o >> 6;
        float acc = b2[s];
#pragma unroll
        for (int j = 0; j < 128; j++) acc = fmaf(hs[r][j], w2[j * 8 + s], acc);
        out[((size_t)b * NT + f * SEG + s) * NN + n0 + r] = acc;
    }
}

// ================= decoder MLP for pred =================
__global__ void __launch_bounds__(256) k_dec_pred(const float* __restrict__ cur,
        const float* __restrict__ w1, const float* __restrict__ b1,
        const float* __restrict__ w2, const float* __restrict__ b2,
        float* __restrict__ out) {
    int n0 = blockIdx.x * 64;
    int t  = blockIdx.y;
    int b  = blockIdx.z;
    const float* src = &cur[(((size_t)b * 23 + MAXK + t) * NN + n0) * 64];
    __shared__ float hs[64][129];
    int tid = threadIdx.x;
    {
        int r = tid >> 2;
        int j0 = (tid & 3) * 32;
        const float* xr = &src[(size_t)r * 64];
        for (int j = j0; j < j0 + 32; j++) {
            float h = b1[j];
#pragma unroll
            for (int c = 0; c < 64; c++) h = fmaf(xr[c], w1[c * 128 + j], h);
            hs[r][j] = fmaxf(h, 0.f);
        }
    }
    __syncthreads();
    for (int o = tid; o < 512; o += 256) {
        int r = o >> 3, s = o & 7;
        float acc = b2[s];
#pragma unroll
        for (int j = 0; j < 128; j++) acc = fmaf(hs[r][j], w2[j * 8 + s], acc);
        out[(size_t)b * (NSTEP * SEG * NN) + (size_t)t * 8192 + (size_t)(n0 + r) * 8 + s] = acc;
    }
}

// ================= host launcher =================
extern "C" void kernel_launch(void* const* d_in, const int* in_sizes, int n_in,
                              void* d_out, int out_size) {
    (void)in_sizes; (void)n_in; (void)out_size;
    const float* x_diff = (const float*)d_in[0];
    const float* adj    = (const float*)d_in[1];
    const float* enc_w1 = (const float*)d_in[2];
    const float* enc_b1 = (const float*)d_in[3];
    const float* enc_w2 = (const float*)d_in[4];
    const float* enc_b2 = (const float*)d_in[5];
    const float* dec_w1 = (const float*)d_in[6];
    const float* dec_b1 = (const float*)d_in[7];
    const float* dec_w2 = (const float*)d_in[8];
    const float* dec_b2 = (const float*)d_in[9];
    const float* g1_w   = (const float*)d_in[10];
    const float* g1_b   = (const float*)d_in[11];
    const float* g2_w   = (const float*)d_in[12];
    const float* g2_b   = (const float*)d_in[13];
    const float* cw[6], *cb[6];
    for (int i = 0; i < 6; i++) {
        cw[i] = (const float*)d_in[14 + 2 * i];
        cb[i] = (const float*)d_in[15 + 2 * i];
    }

    float* scratch = nullptr;
    cudaGetSymbolAddress((void**)&scratch, g_scratch);
    float* a1    = scratch + OFF_A1;
    float* a2    = scratch + OFF_A2;
    float* wcT   = scratch + OFF_WCT;
    float* bsum  = scratch + OFF_BSUM;
    float* ec    = scratch + OFF_EC;
    float* eb    = scratch + OFF_EB;
    float* res   = scratch + OFF_RES;
    float* conv  = scratch + OFF_CONV;
    float* h1a   = scratch + OFF_H1A;
    float* h2a   = scratch + OFF_H2A;
    float* h1b   = scratch + OFF_H1B;
    float* h2b   = scratch + OFF_H2B;
    float* stout = scratch + OFF_STOUT;
    float* cur   = scratch + OFF_CUR;
    float* tcl   = scratch + OFF_TCL;
    float* ph1a  = scratch + OFF_PH1A;
    float* ph1b  = scratch + OFF_PH1B;
    float* ph2a  = scratch + OFF_PH2A;
    float* ph2b  = scratch + OFF_PH2B;
    float* part  = scratch + OFF_PART;

    float* rec_out  = (float*)d_out;
    float* pred_out = rec_out + (size_t)NB * NT * NN;

    // ---- preprocessing ----
    k_norm_adj<<<NN, 256>>>(adj, a1, a2);
    k_comb_w<<<(11 * 64 * 64 + 255) / 256, 256>>>(cw[0], cw[1], cw[2], cw[3], cw[4], cw[5],
                                                  cb[0], cb[1], cb[2], cb[3], cb[4], cb[5],
                                                  wcT, bsum);
    k_comb_g<<<80, 256>>>(g1_w, g1_b, g2_w, g2_b, ec, eb);

    // ---- encoder ----
    k_enc<<<dim3(16, FREQ, NB), 256>>>(x_diff, enc_w1, enc_b1, enc_w2, enc_b2, res);

    // ---- rec-path stconv ----
    k_tconv<<<dim3(8, NB * TREC), 256>>>(res, wcT, bsum, conv);
    k_prop128<<<dim3(8, NB * TREC / 2, 2), 256>>>(a1, a2, conv, conv, h1a, h1b);
    k_prop128<<<dim3(8, NB * TREC / 2, 2), 256>>>(a1, a2, h1a, h1b, h2a, h2b);
    k_combine<<<dim3(8, NB * TREC), 256>>>(conv, h1a, h2a, h1b, h2b, ec, eb,
                                           res, stout,
                                           TREC, FREQ, 0,
                                           TREC, TREC, 0);
    // ---- rec decoder ----
    k_dec_rec<<<dim3(16, FREQ, NB), 256>>>(res, stout, dec_w1, dec_b1, dec_w2, dec_b2, rec_out);

    // ---- autoregressive loop ----
    k_cur_init<<<4096, 256>>>(res, cur);
    for (int s = 0; s < NSTEP; s++) {
        k_tcl<<<64, 256>>>(cur, wcT, bsum, tcl, s);
        k_prop_sk<<<dim3(8, 4, 8), 256>>>(a1, a2, tcl, tcl, part);
        k_reduce4<<<512, 256>>>(part, ph1a, ph1b);
        k_prop_sk<<<dim3(8, 4, 8), 256>>>(a1, a2, ph1a, ph1b, part);
        k_reduce4<<<512, 256>>>(part, ph2a, ph2b);
        k_combine<<<dim3(8, NB), 256>>>(tcl, ph1a, ph2a, ph1b, ph2b, ec, eb,
                                        cur, cur,
                                        1, 23, s + 10,
                                        1, 23, s + 11);
    }
    // ---- pred decoder ----
    k_dec_pred<<<dim3(16, NSTEP, NB), 256>>>(cur, dec_w1, dec_b1, dec_w2, dec_b2, pred_out);
}

// round 6
// speedup vs baseline: 1.6173x; 1.3201x over previous
#include <cuda_runtime.h>
#include <cstdint>

// ---------------- problem constants ----------------
#define NB   8
#define NT   336
#define NN   1024
#define FREQ 42
#define SEG  8
#define TREC 41
#define NSTEP 12
#define MAXK 11
#define ALPHA 0.05f
#define BETA  0.95f

// ---------------- scratch layout (floats) ----------------
static const size_t OFF_A1   = 0;                         // 1024*1024
static const size_t OFF_A2   = OFF_A1   + 1048576;
static const size_t OFF_WCT  = OFF_A2   + 1048576;        // 11*64*64
static const size_t OFF_BSUM = OFF_WCT  + 45056;          // 64
static const size_t OFF_EC   = OFF_BSUM + 64;             // 5*64*64
static const size_t OFF_EB   = OFF_EC   + 20480;          // 64
static const size_t OFF_RES  = OFF_EB   + 64;             // 8*42*1024*64
static const size_t OFF_CONV = OFF_RES  + 22020096;       // 8*41*1024*64
static const size_t OFF_H1A  = OFF_CONV + 21495808;
static const size_t OFF_H2A  = OFF_H1A  + 21495808;
static const size_t OFF_H1B  = OFF_H2A  + 21495808;
static const size_t OFF_H2B  = OFF_H1B  + 21495808;
static const size_t OFF_STOUT= OFF_H2B  + 21495808;
static const size_t OFF_CUR  = OFF_STOUT+ 21495808;       // 8*23*1024*64
static const size_t OFF_TCL  = OFF_CUR  + 12058624;       // 8*1024*64
static const size_t OFF_PH1A = OFF_TCL  + 524288;
static const size_t OFF_PH1B = OFF_PH1A + 524288;
static const size_t OFF_PH2A = OFF_PH1B + 524288;
static const size_t OFF_PH2B = OFF_PH2A + 524288;
static const size_t OFF_PART = OFF_PH2B + 524288;         // 8 slots * 8*1024*64
static const size_t SCRATCH_TOTAL = OFF_PART + 4194304;

__device__ float g_scratch[SCRATCH_TOTAL];

// =====================================================================
// GEMM64 chunk macro: accumulates C[128 x 64] += Asrc[128 x 64] @ Bsrc[64 x 64]
// Asrc: 128 rows (ld=64, k contiguous). Bsrc: k-major [k][n], ld=64.
// Needs in scope: __shared__ float As[16][132], Bs[16][68];
//                 int tid, tx (tid&15), ty (tid>>4); float acc[8][4].
// Microtile rows: {ty*4+i, 64+ty*4+i}, cols: tx*4+j.
// =====================================================================
#define GEMM64_CHUNK(ASRC, BSRC) do {                                          \
    const float* _as = (ASRC); const float* _bs = (BSRC);                      \
    for (int k0 = 0; k0 < 64; k0 += 16) {                                      \
        _Pragma("unroll")                                                      \
        for (int i = 0; i < 2; i++) {                                          \
            int li = tid + i * 256;                                            \
            int m = li & 127, k4 = li >> 7;                                    \
            float4 v = *(const float4*)&_as[(size_t)m * 64 + k0 + k4 * 4];     \
            As[k4*4+0][m] = v.x; As[k4*4+1][m] = v.y;                          \
            As[k4*4+2][m] = v.z; As[k4*4+3][m] = v.w;                          \
        }                                                                      \
        {                                                                      \
            int kk = tid >> 4, n4 = (tid & 15) * 4;                            \
            *(float4*)&Bs[kk][n4] =                                            \
                *(const float4*)&_bs[(size_t)(k0 + kk) * 64 + n4];             \
        }                                                                      \
        __syncthreads();                                                       \
        _Pragma("unroll")                                                      \
        for (int k = 0; k < 16; k++) {                                         \
            float a_[8], b_[4];                                                \
            *(float4*)&a_[0] = *(const float4*)&As[k][ty * 4];                 \
            *(float4*)&a_[4] = *(const float4*)&As[k][64 + ty * 4];            \
            *(float4*)&b_[0] = *(const float4*)&Bs[k][tx * 4];                 \
            _Pragma("unroll")                                                  \
            for (int i = 0; i < 8; i++) {                                      \
                _Pragma("unroll")                                              \
                for (int j = 0; j < 4; j++)                                    \
                    acc[i][j] = fmaf(a_[i], b_[j], acc[i][j]);                 \
            }                                                                  \
        }                                                                      \
        __syncthreads();                                                       \
    }                                                                          \
} while (0)

// ================= adjacency normalization =================
__global__ void k_norm_adj(const float* __restrict__ adj,
                           float* __restrict__ a1, float* __restrict__ a2) {
    int v = blockIdx.x;
    int tid = threadIdx.x;
    __shared__ float r1[256], r2[256];
    float s1 = 0.f, s2 = 0.f;
    for (int n = tid; n < NN; n += 256) {
        s1 += adj[(size_t)v * NN + n];
        s2 += adj[(size_t)n * NN + v];
    }
    r1[tid] = s1; r2[tid] = s2;
    __syncthreads();
    for (int off = 128; off > 0; off >>= 1) {
        if (tid < off) { r1[tid] += r1[tid + off]; r2[tid] += r2[tid + off]; }
        __syncthreads();
    }
    float inv1 = 1.f / (r1[0] + 1.f);
    float inv2 = 1.f / (r2[0] + 1.f);
    for (int n = tid; n < NN; n += 256) {
        float d = (n == v) ? 1.f : 0.f;
        a1[(size_t)v * NN + n] = (adj[(size_t)v * NN + n] + d) * inv1;
        a2[(size_t)v * NN + n] = (adj[(size_t)n * NN + v] + d) * inv2;
    }
}

// ================= combine conv weights =================
__global__ void k_comb_w(const float* w0, const float* w1, const float* w2,
                         const float* w3, const float* w4, const float* w5,
                         const float* cb0, const float* cb1, const float* cb2,
                         const float* cb3, const float* cb4, const float* cb5,
                         float* __restrict__ wcT, float* __restrict__ bsum) {
    int idx = blockIdx.x * 256 + threadIdx.x;
    if (idx >= 11 * 64 * 64) return;
    int o = idx & 63;
    int c = (idx >> 6) & 63;
    int dt = idx >> 12;
    int dv = dt - 5;
    int ad = dv < 0 ? -dv : dv;
    const float* ws[6] = {w0, w1, w2, w3, w4, w5};
    float acc = 0.f;
    for (int i = ad; i < 6; i++) {
        int K = 2 * i + 1;
        acc += ws[i][(size_t)(o * 64 + c) * K + (dv + i)];
    }
    wcT[((size_t)dt * 64 + c) * 64 + o] = acc;
    if (dt == 0 && c == 0)
        bsum[o] = cb0[o] + cb1[o] + cb2[o] + cb3[o] + cb4[o] + cb5[o];
}

// ================= combine mixprop weights =================
__global__ void k_comb_g(const float* __restrict__ g1w, const float* __restrict__ g1b,
                         const float* __restrict__ g2w, const float* __restrict__ g2b,
                         float* __restrict__ ec, float* __restrict__ eb) {
    int idx = blockIdx.x * 256 + threadIdx.x;
    if (idx >= 5 * 4096) return;
    int term = idx >> 12;
    int co = idx & 4095;    // c*64+o
    float v;
    if (term == 0) {
        v = g1w[co] + ALPHA * (g1w[4096 + co] + g1w[8192 + co])
          + g2w[co] + ALPHA * (g2w[4096 + co] + g2w[8192 + co]);
    } else if (term == 1) {
        v = BETA * g1w[4096 + co] + ALPHA * BETA * g1w[8192 + co];
    } else if (term == 2) {
        v = BETA * BETA * g1w[8192 + co];
    } else if (term == 3) {
        v = BETA * g2w[4096 + co] + ALPHA * BETA * g2w[8192 + co];
    } else {
        v = BETA * BETA * g2w[8192 + co];
    }
    ec[idx] = v;
    if (idx < 64) eb[idx] = g1b[idx] + g2b[idx];
}

// ================= encoder MLP (two-stage tiled GEMM) =================
__global__ void __launch_bounds__(256) k_enc2(const float* __restrict__ x,
        const float* __restrict__ w1, const float* __restrict__ b1,
        const float* __restrict__ w2, const float* __restrict__ b2,
        float* __restrict__ out) {
    extern __shared__ float sm[];
    float* xst = sm;                    // [8][132]   x transposed (k-major)
    float* w1s = xst + 8 * 132;         // [8*128]
    float* hst = w1s + 1024;            // [128][132] hidden transposed
    float* Bs  = hst + 128 * 132;       // [16][68]
    int n0 = blockIdx.x * 128;
    int f  = blockIdx.y;
    int b  = blockIdx.z;
    int tid = threadIdx.x, tx = tid & 15, ty = tid >> 4;

#pragma unroll
    for (int it = 0; it < 4; it++) {
        int li = tid + it * 256;
        int s = li >> 7, m = li & 127;
        xst[s * 132 + m] = x[((size_t)b * NT + f * SEG + s) * NN + n0 + m];
        w1s[li] = w1[li];
    }
    __syncthreads();

    // stage 1: hT[j][m] = relu(b1[j] + sum_s w1[s][j]*x[m][s])
    float acc1[8][8] = {};
#pragma unroll
    for (int k = 0; k < 8; k++) {
        float a_[8], b_[8];
        *(float4*)&a_[0] = *(const float4*)&w1s[k * 128 + ty * 4];
        *(float4*)&a_[4] = *(const float4*)&w1s[k * 128 + 64 + ty * 4];
        *(float4*)&b_[0] = *(const float4*)&xst[k * 132 + tx * 4];
        *(float4*)&b_[4] = *(const float4*)&xst[k * 132 + 64 + tx * 4];
#pragma unroll
        for (int i = 0; i < 8; i++)
#pragma unroll
            for (int j = 0; j < 8; j++)
                acc1[i][j] = fmaf(a_[i], b_[j], acc1[i][j]);
    }
#pragma unroll
    for (int i = 0; i < 8; i++) {
        int j = (i < 4) ? ty * 4 + i : 64 + ty * 4 + (i - 4);
        float bb = b1[j];
        float4 v0, v1;
        v0.x = fmaxf(acc1[i][0] + bb, 0.f); v0.y = fmaxf(acc1[i][1] + bb, 0.f);
        v0.z = fmaxf(acc1[i][2] + bb, 0.f); v0.w = fmaxf(acc1[i][3] + bb, 0.f);
        v1.x = fmaxf(acc1[i][4] + bb, 0.f); v1.y = fmaxf(acc1[i][5] + bb, 0.f);
        v1.z = fmaxf(acc1[i][6] + bb, 0.f); v1.w = fmaxf(acc1[i][7] + bb, 0.f);
        *(float4*)&hst[j * 132 + tx * 4]      = v0;
        *(float4*)&hst[j * 132 + 64 + tx * 4] = v1;
    }
    __syncthreads();

    // stage 2: out[m][d] = b2[d] + sum_j hst[j][m] * w2[j][d]
    float acc2[8][4] = {};
    for (int k0 = 0; k0 < 128; k0 += 16) {
        {
            int kk = tid >> 4, n4 = (tid & 15) * 4;
            *(float4*)&Bs[kk * 68 + n4] = *(const float4*)&w2[(size_t)(k0 + kk) * 64 + n4];
        }
        __syncthreads();
#pragma unroll
        for (int k = 0; k < 16; k++) {
            float a_[8], b_[4];
            *(float4*)&a_[0] = *(const float4*)&hst[(k0 + k) * 132 + ty * 4];
            *(float4*)&a_[4] = *(const float4*)&hst[(k0 + k) * 132 + 64 + ty * 4];
            *(float4*)&b_[0] = *(const float4*)&Bs[k * 68 + tx * 4];
#pragma unroll
            for (int i = 0; i < 8; i++)
#pragma unroll
                for (int j = 0; j < 4; j++)
                    acc2[i][j] = fmaf(a_[i], b_[j], acc2[i][j]);
        }
        __syncthreads();
    }
    float4 b2v = *(const float4*)&b2[tx * 4];
#pragma unroll
    for (int i = 0; i < 8; i++) {
        int m = n0 + ((i < 4) ? ty * 4 + i : 64 + ty * 4 + (i - 4));
        float4 v;
        v.x = acc2[i][0] + b2v.x; v.y = acc2[i][1] + b2v.y;
        v.z = acc2[i][2] + b2v.z; v.w = acc2[i][3] + b2v.w;
        *(float4*)&out[(((size_t)b * FREQ + f) * NN + m) * 64 + tx * 4] = v;
    }
}

// ================= decoder MLP common stage-1 macro =================
// builds hst[j][m] = relu(b1[j] + sum_c w1[c][j]*src[m][c]) for 128 rows
#define DEC_STAGE1(SRC) do {                                                   \
    float acc1[8][8] = {};                                                     \
    for (int k0 = 0; k0 < 64; k0 += 16) {                                      \
        _Pragma("unroll")                                                      \
        for (int it = 0; it < 2; it++) {                                       \
            int f4 = tid + it * 256;                                           \
            int kk = f4 >> 5, j4 = (f4 & 31) * 4;                              \
            *(float4*)&As1[kk * 132 + j4] =                                    \
                *(const float4*)&w1[(size_t)(k0 + kk) * 128 + j4];             \
        }                                                                      \
        _Pragma("unroll")                                                      \
        for (int it = 0; it < 2; it++) {                                       \
            int li = tid + it * 256;                                           \
            int m = li & 127, k4 = li >> 7;                                    \
            float4 v = *(const float4*)&(SRC)[(size_t)m * 64 + k0 + k4 * 4];   \
            Bs1[(k4*4+0)*132 + m] = v.x; Bs1[(k4*4+1)*132 + m] = v.y;          \
            Bs1[(k4*4+2)*132 + m] = v.z; Bs1[(k4*4+3)*132 + m] = v.w;          \
        }                                                                      \
        __syncthreads();                                                       \
        _Pragma("unroll")                                                      \
        for (int k = 0; k < 16; k++) {                                         \
            float a_[8], b_[8];                                                \
            *(float4*)&a_[0] = *(const float4*)&As1[k * 132 + ty * 4];         \
            *(float4*)&a_[4] = *(const float4*)&As1[k * 132 + 64 + ty * 4];    \
            *(float4*)&b_[0] = *(const float4*)&Bs1[k * 132 + tx * 4];         \
            *(float4*)&b_[4] = *(const float4*)&Bs1[k * 132 + 64 + tx * 4];    \
            _Pragma("unroll")                                                  \
            for (int i = 0; i < 8; i++)                                        \
                _Pragma("unroll")                                              \
                for (int j = 0; j < 8; j++)                                    \
                    acc1[i][j] = fmaf(a_[i], b_[j], acc1[i][j]);               \
        }                                                                      \
        __syncthreads();                                                       \
    }                                                                          \
    _Pragma("unroll")                                                          \
    for (int i = 0; i < 8; i++) {                                              \
        int j = (i < 4) ? ty * 4 + i : 64 + ty * 4 + (i - 4);                  \
        float bb = b1[j];                                                      \
        float4 v0, v1;                                                         \
        v0.x = fmaxf(acc1[i][0] + bb, 0.f); v0.y = fmaxf(acc1[i][1] + bb, 0.f);\
        v0.z = fmaxf(acc1[i][2] + bb, 0.f); v0.w = fmaxf(acc1[i][3] + bb, 0.f);\
        v1.x = fmaxf(acc1[i][4] + bb, 0.f); v1.y = fmaxf(acc1[i][5] + bb, 0.f);\
        v1.z = fmaxf(acc1[i][6] + bb, 0.f); v1.w = fmaxf(acc1[i][7] + bb, 0.f);\
        *(float4*)&hst[j * 132 + tx * 4]      = v0;                            \
        *(float4*)&hst[j * 132 + 64 + tx * 4] = v1;                            \
    }                                                                          \
    __syncthreads();                                                           \
} while (0)

// stage 2 (shared): each thread: row m=tid>>1, 4 outputs starting at sg*4.
// m and sg must be declared by the caller.
#define DEC_STAGE2(A4, M_, SG_) do {                                           \
    M_ = tid >> 1; SG_ = tid & 1;                                              \
    A4[0] = b2[SG_ * 4 + 0]; A4[1] = b2[SG_ * 4 + 1];                          \
    A4[2] = b2[SG_ * 4 + 2]; A4[3] = b2[SG_ * 4 + 3];                          \
    _Pragma("unroll 4")                                                        \
    for (int j = 0; j < 128; j++) {                                            \
        float h = hst[j * 132 + M_];                                           \
        float4 w = *(const float4*)&w2s[j * 8 + SG_ * 4];                      \
        A4[0] = fmaf(h, w.x, A4[0]); A4[1] = fmaf(h, w.y, A4[1]);              \
        A4[2] = fmaf(h, w.z, A4[2]); A4[3] = fmaf(h, w.w, A4[3]);              \
    }                                                                          \
} while (0)

// ================= decoder MLP for rec =================
__global__ void __launch_bounds__(256) k_dec_rec2(const float* __restrict__ res,
        const float* __restrict__ stout,
        const float* __restrict__ w1, const float* __restrict__ b1,
        const float* __restrict__ w2, const float* __restrict__ b2,
        float* __restrict__ out) {
    extern __shared__ float sm[];
    float* As1 = sm;                    // [16][132]
    float* Bs1 = As1 + 16 * 132;        // [16][132]
    float* hst = Bs1 + 16 * 132;        // [128][132]
    float* w2s = hst + 128 * 132;       // [128*8]
    int n0 = blockIdx.x * 128;
    int f  = blockIdx.y;
    int b  = blockIdx.z;
    int tid = threadIdx.x, tx = tid & 15, ty = tid >> 4;
    const float* src = (f == 0)
        ? &res[(((size_t)b * FREQ) * NN + n0) * 64]
        : &stout[(((size_t)b * TREC + f - 1) * NN + n0) * 64];
#pragma unroll
    for (int it = 0; it < 4; it++) w2s[tid + it * 256] = w2[tid + it * 256];
    DEC_STAGE1(src);
    float a4[4];
    int m, sg;
    DEC_STAGE2(a4, m, sg);
#pragma unroll
    for (int q = 0; q < 4; q++) {
        int s = sg * 4 + q;
        out[((size_t)b * NT + f * SEG + s) * NN + n0 + m] = a4[q];
    }
}

// ================= decoder MLP for pred =================
__global__ void __launch_bounds__(256) k_dec_pred2(const float* __restrict__ cur,
        const float* __restrict__ w1, const float* __restrict__ b1,
        const float* __restrict__ w2, const float* __restrict__ b2,
        float* __restrict__ out) {
    extern __shared__ float sm[];
    float* As1 = sm;
    float* Bs1 = As1 + 16 * 132;
    float* hst = Bs1 + 16 * 132;
    float* w2s = hst + 128 * 132;
    int n0 = blockIdx.x * 128;
    int t  = blockIdx.y;
    int b  = blockIdx.z;
    int tid = threadIdx.x, tx = tid & 15, ty = tid >> 4;
    const float* src = &cur[(((size_t)b * 23 + MAXK + t) * NN + n0) * 64];
#pragma unroll
    for (int it = 0; it < 4; it++) w2s[tid + it * 256] = w2[tid + it * 256];
    DEC_STAGE1(src);
    float a4[4];
    int m, sg;
    DEC_STAGE2(a4, m, sg);
    float4 v = make_float4(a4[0], a4[1], a4[2], a4[3]);
    *(float4*)&out[(size_t)b * (NSTEP * SEG * NN) + (size_t)t * 8192
                   + (size_t)(n0 + m) * 8 + sg * 4] = v;
}

// ================= t_inception (rec path), 128x64 tiles =================
__global__ void __launch_bounds__(256) k_tconv(const float* __restrict__ res,
        const float* __restrict__ wcT, const float* __restrict__ bsum,
        float* __restrict__ out) {
    int m0 = blockIdx.x * 128;
    int bt = blockIdx.y;
    int b = bt / TREC, t = bt % TREC;
    __shared__ float As[16][132];
    __shared__ float Bs[16][68];
    int tid = threadIdx.x;
    int tx = tid & 15, ty = tid >> 4;
    float acc[8][4] = {};
    for (int dt = 0; dt < MAXK; dt++) {
        int ts = t + dt - 5;
        if (ts < 0 || ts >= TREC) continue;
        GEMM64_CHUNK(&res[(((size_t)b * FREQ + ts) * NN + m0) * 64],
                     &wcT[(size_t)dt * 4096]);
    }
    const float inv6 = 1.f / 6.f;
    float4 bsv = *(const float4*)&bsum[tx * 4];
    float bsa[4] = {bsv.x, bsv.y, bsv.z, bsv.w};
#pragma unroll
    for (int i = 0; i < 8; i++) {
        int m = m0 + (i < 4 ? ty * 4 + i : 60 + ty * 4 + i);
        float4 v;
        v.x = (acc[i][0] + bsa[0]) * inv6;
        v.y = (acc[i][1] + bsa[1]) * inv6;
        v.z = (acc[i][2] + bsa[2]) * inv6;
        v.w = (acc[i][3] + bsa[3]) * inv6;
        *(float4*)&out[((size_t)bt * NN + m) * 64 + tx * 4] = v;
    }
}

// ================= rec prop: raw A@h, 128x128 tiles, bt-paired, dir in z =====
__global__ void __launch_bounds__(256) k_prop128(
        const float* __restrict__ a1, const float* __restrict__ a2,
        const float* __restrict__ hin0, const float* __restrict__ hin1,
        float* __restrict__ hout0, float* __restrict__ hout1) {
    const float* A    = blockIdx.z ? a2 : a1;
    const float* hin  = blockIdx.z ? hin1 : hin0;
    float*       hout = blockIdx.z ? hout1 : hout0;
    int m0 = blockIdx.x * 128;
    size_t base0 = (size_t)(2 * blockIdx.y) * (NN * 64);
    size_t base1 = base0 + (size_t)NN * 64;
    __shared__ float As[16][132];
    __shared__ float Bs[16][132];
    int tid = threadIdx.x;
    int tx = tid & 15, ty = tid >> 4;
    float acc[8][8] = {};
    for (int k0 = 0; k0 < NN; k0 += 16) {
#pragma unroll
        for (int i = 0; i < 2; i++) {
            int li = tid + i * 256;
            int m = li & 127, k4 = li >> 7;
            float4 v = *(const float4*)&A[(size_t)(m0 + m) * NN + k0 + k4 * 4];
            As[k4*4+0][m] = v.x; As[k4*4+1][m] = v.y;
            As[k4*4+2][m] = v.z; As[k4*4+3][m] = v.w;
        }
#pragma unroll
        for (int i = 0; i < 2; i++) {
            int li = tid + i * 256;
            int kk = li >> 5;
            int n4 = (li & 31) * 4;
            size_t src = (n4 < 64) ? base0 + (size_t)(k0 + kk) * 64 + n4
                                   : base1 + (size_t)(k0 + kk) * 64 + (n4 - 64);
            *(float4*)&Bs[kk][n4] = *(const float4*)&hin[src];
        }
        __syncthreads();
#pragma unroll
        for (int k = 0; k < 16; k++) {
            float a_[8], b_[8];
            *(float4*)&a_[0] = *(const float4*)&As[k][ty * 4];
            *(float4*)&a_[4] = *(const float4*)&As[k][64 + ty * 4];
            *(float4*)&b_[0] = *(const float4*)&Bs[k][tx * 4];
            *(float4*)&b_[4] = *(const float4*)&Bs[k][64 + tx * 4];
#pragma unroll
            for (int i = 0; i < 8; i++)
#pragma unroll
                for (int j = 0; j < 8; j++)
                    acc[i][j] = fmaf(a_[i], b_[j], acc[i][j]);
        }
        __syncthreads();
    }
    float* o0 = hout + base0 + (size_t)m0 * 64;
    float* o1 = hout + base1 + (size_t)m0 * 64;
#pragma unroll
    for (int i = 0; i < 8; i++) {
        int m = (i < 4 ? ty * 4 + i : 60 + ty * 4 + i);
        float4 v0 = make_float4(acc[i][0], acc[i][1], acc[i][2], acc[i][3]);
        float4 v1 = make_float4(acc[i][4], acc[i][5], acc[i][6], acc[i][7]);
        *(float4*)&o0[(size_t)m * 64 + tx * 4] = v0;
        *(float4*)&o1[(size_t)m * 64 + tx * 4] = v1;
    }
}

// ================= AR prop with split-K=4, b-paired, (dir,chunk) in z ========
__global__ void __launch_bounds__(256) k_prop_sk(
        const float* __restrict__ a1, const float* __restrict__ a2,
        const float* __restrict__ hin0, const float* __restrict__ hin1,
        float* __restrict__ part) {
    int dir = blockIdx.z >> 2;
    int chunk = blockIdx.z & 3;
    const float* A   = dir ? a2 : a1;
    const float* hin = dir ? hin1 : hin0;
    int m0 = blockIdx.x * 128;
    int b0 = 2 * blockIdx.y, b1 = b0 + 1;
    size_t base0 = (size_t)b0 * (NN * 64);
    size_t base1 = (size_t)b1 * (NN * 64);
    __shared__ float As[16][132];
    __shared__ float Bs[16][132];
    int tid = threadIdx.x;
    int tx = tid & 15, ty = tid >> 4;
    float acc[8][8] = {};
    int kend = chunk * 256 + 256;
    for (int k0 = chunk * 256; k0 < kend; k0 += 16) {
#pragma unroll
        for (int i = 0; i < 2; i++) {
            int li = tid + i * 256;
            int m = li & 127, k4 = li >> 7;
            float4 v = *(const float4*)&A[(size_t)(m0 + m) * NN + k0 + k4 * 4];
            As[k4*4+0][m] = v.x; As[k4*4+1][m] = v.y;
            As[k4*4+2][m] = v.z; As[k4*4+3][m] = v.w;
        }
#pragma unroll
        for (int i = 0; i < 2; i++) {
            int li = tid + i * 256;
            int kk = li >> 5;
            int n4 = (li & 31) * 4;
            size_t src = (n4 < 64) ? base0 + (size_t)(k0 + kk) * 64 + n4
                                   : base1 + (size_t)(k0 + kk) * 64 + (n4 - 64);
            *(float4*)&Bs[kk][n4] = *(const float4*)&hin[src];
        }
        __syncthreads();
#pragma unroll
        for (int k = 0; k < 16; k++) {
            float a_[8], b_[8];
            *(float4*)&a_[0] = *(const float4*)&As[k][ty * 4];
            *(float4*)&a_[4] = *(const float4*)&As[k][64 + ty * 4];
            *(float4*)&b_[0] = *(const float4*)&Bs[k][tx * 4];
            *(float4*)&b_[4] = *(const float4*)&Bs[k][64 + tx * 4];
#pragma unroll
            for (int i = 0; i < 8; i++)
#pragma unroll
                for (int j = 0; j < 8; j++)
                    acc[i][j] = fmaf(a_[i], b_[j], acc[i][j]);
        }
        __syncthreads();
    }
    int slot = (dir * 4 + chunk) * NB;
    float* o0 = part + ((size_t)(slot + b0)) * (NN * 64) + (size_t)m0 * 64;
    float* o1 = part + ((size_t)(slot + b1)) * (NN * 64) + (size_t)m0 * 64;
#pragma unroll
    for (int i = 0; i < 8; i++) {
        int m = (i < 4 ? ty * 4 + i : 60 + ty * 4 + i);
        float4 v0 = make_float4(acc[i][0], acc[i][1], acc[i][2], acc[i][3]);
        float4 v1 = make_float4(acc[i][4], acc[i][5], acc[i][6], acc[i][7]);
        *(float4*)&o0[(size_t)m * 64 + tx * 4] = v0;
        *(float4*)&o1[(size_t)m * 64 + tx * 4] = v1;
    }
}

// ================= split-K reduce: sums 4 chunks per dir =================
__global__ void k_reduce4(const float* __restrict__ part,
                          float* __restrict__ o0, float* __restrict__ o1) {
    const size_t S = (size_t)NB * NN * 64;   // 524288 per slot
    size_t i = ((size_t)blockIdx.x * blockDim.x + threadIdx.x) * 4;
    if (i >= S) return;
    float4 a = *(const float4*)&part[i];
    float4 b = *(const float4*)&part[S + i];
    float4 c = *(const float4*)&part[2 * S + i];
    float4 d = *(const float4*)&part[3 * S + i];
    float4 r = make_float4(a.x + b.x + c.x + d.x, a.y + b.y + c.y + d.y,
                           a.z + b.z + c.z + d.z, a.w + b.w + c.w + d.w);
    *(float4*)&o0[i] = r;
    a = *(const float4*)&part[4 * S + i];
    b = *(const float4*)&part[5 * S + i];
    c = *(const float4*)&part[6 * S + i];
    d = *(const float4*)&part[7 * S + i];
    r = make_float4(a.x + b.x + c.x + d.x, a.y + b.y + c.y + d.y,
                    a.z + b.z + c.z + d.z, a.w + b.w + c.w + d.w);
    *(float4*)&o1[i] = r;
}

// ================= combine (5-term) + bias + residual =================
__global__ void __launch_bounds__(256) k_combine(const float* __restrict__ x,
        const float* __restrict__ s1, const float* __restrict__ s2,
        const float* __restrict__ t1, const float* __restrict__ t2,
        const float* __restrict__ ec, const float* __restrict__ eb,
        const float* __restrict__ resid, float* __restrict__ out,
        int rdiv, int rmul, int roff,
        int odiv, int omul, int ooff) {
    int m0 = blockIdx.x * 128;
    int bt = blockIdx.y;
    size_t base = (size_t)bt * (NN * 64) + (size_t)m0 * 64;
    __shared__ float As[16][132];
    __shared__ float Bs[16][68];
    int tid = threadIdx.x;
    int tx = tid & 15, ty = tid >> 4;
    float acc[8][4] = {};
    GEMM64_CHUNK(x  + base, ec);
    GEMM64_CHUNK(s1 + base, ec + 4096);
    GEMM64_CHUNK(s2 + base, ec + 8192);
    GEMM64_CHUNK(t1 + base, ec + 12288);
    GEMM64_CHUNK(t2 + base, ec + 16384);
    int rrow = (bt / rdiv) * rmul + (bt % rdiv) + roff;
    int orow = (bt / odiv) * omul + (bt % odiv) + ooff;
    float4 ebv = *(const float4*)&eb[tx * 4];
    float eba[4] = {ebv.x, ebv.y, ebv.z, ebv.w};
#pragma unroll
    for (int i = 0; i < 8; i++) {
        int m = m0 + (i < 4 ? ty * 4 + i : 60 + ty * 4 + i);
        float4 rv = *(const float4*)&resid[((size_t)rrow * NN + m) * 64 + tx * 4];
        float4 v;
        v.x = acc[i][0] + eba[0] + rv.x;
        v.y = acc[i][1] + eba[1] + rv.y;
        v.z = acc[i][2] + eba[2] + rv.z;
        v.w = acc[i][3] + eba[3] + rv.w;
        *(float4*)&out[((size_t)orow * NN + m) * 64 + tx * 4] = v;
    }
}

// ================= AR last-timestep inception, 128x64 tiles =================
__global__ void __launch_bounds__(256) k_tcl(const float* __restrict__ cur,
        const float* __restrict__ wcT, const float* __restrict__ bsum,
        float* __restrict__ out, int s) {
    int gm = blockIdx.x;           // 0..63
    int b  = gm >> 3;
    int m0 = (gm & 7) * 128;
    __shared__ float As[16][132];
    __shared__ float Bs[16][68];
    int tid = threadIdx.x;
    int tx = tid & 15, ty = tid >> 4;
    float acc[8][4] = {};
    for (int j = 0; j < 6; j++) {
        GEMM64_CHUNK(&cur[(((size_t)b * 23 + s + 5 + j) * NN + m0) * 64],
                     &wcT[(size_t)j * 4096]);
    }
    const float inv6 = 1.f / 6.f;
    float4 bsv = *(const float4*)&bsum[tx * 4];
    float bsa[4] = {bsv.x, bsv.y, bsv.z, bsv.w};
#pragma unroll
    for (int i = 0; i < 8; i++) {
        int m = m0 + (i < 4 ? ty * 4 + i : 60 + ty * 4 + i);
        float4 v;
        v.x = (acc[i][0] + bsa[0]) * inv6;
        v.y = (acc[i][1] + bsa[1]) * inv6;
        v.z = (acc[i][2] + bsa[2]) * inv6;
        v.w = (acc[i][3] + bsa[3]) * inv6;
        *(float4*)&out[((size_t)b * NN + m) * 64 + tx * 4] = v;
    }
}

// ================= AR cur-buffer init =================
__global__ void k_cur_init(const float* __restrict__ res, float* __restrict__ cur) {
    size_t total = (size_t)NB * MAXK * NN * 64;
    for (size_t idx = (size_t)blockIdx.x * blockDim.x + threadIdx.x; idx < total;
         idx += (size_t)gridDim.x * blockDim.x) {
        int d = idx & 63;
        int n = (idx >> 6) & 1023;
        int j = (int)((idx >> 16) % MAXK);
        int b = (int)(idx / ((size_t)MAXK << 16));
        cur[(((size_t)b * 23 + j) * NN + n) * 64 + d] =
            res[(((size_t)b * FREQ + 31 + j) * NN + n) * 64 + d];
    }
}

// ================= host launcher =================
extern "C" void kernel_launch(void* const* d_in, const int* in_sizes, int n_in,
                              void* d_out, int out_size) {
    (void)in_sizes; (void)n_in; (void)out_size;
    const float* x_diff = (const float*)d_in[0];
    const float* adj    = (const float*)d_in[1];
    const float* enc_w1 = (const float*)d_in[2];
    const float* enc_b1 = (const float*)d_in[3];
    const float* enc_w2 = (const float*)d_in[4];
    const float* enc_b2 = (const float*)d_in[5];
    const float* dec_w1 = (const float*)d_in[6];
    const float* dec_b1 = (const float*)d_in[7];
    const float* dec_w2 = (const float*)d_in[8];
    const float* dec_b2 = (const float*)d_in[9];
    const float* g1_w   = (const float*)d_in[10];
    const float* g1_b   = (const float*)d_in[11];
    const float* g2_w   = (const float*)d_in[12];
    const float* g2_b   = (const float*)d_in[13];
    const float* cw[6], *cb[6];
    for (int i = 0; i < 6; i++) {
        cw[i] = (const float*)d_in[14 + 2 * i];
        cb[i] = (const float*)d_in[15 + 2 * i];
    }

    float* scratch = nullptr;
    cudaGetSymbolAddress((void**)&scratch, g_scratch);
    float* a1    = scratch + OFF_A1;
    float* a2    = scratch + OFF_A2;
    float* wcT   = scratch + OFF_WCT;
    float* bsum  = scratch + OFF_BSUM;
    float* ec    = scratch + OFF_EC;
    float* eb    = scratch + OFF_EB;
    float* res   = scratch + OFF_RES;
    float* conv  = scratch + OFF_CONV;
    float* h1a   = scratch + OFF_H1A;
    float* h2a   = scratch + OFF_H2A;
    float* h1b   = scratch + OFF_H1B;
    float* h2b   = scratch + OFF_H2B;
    float* stout = scratch + OFF_STOUT;
    float* cur   = scratch + OFF_CUR;
    float* tcl   = scratch + OFF_TCL;
    float* ph1a  = scratch + OFF_PH1A;
    float* ph1b  = scratch + OFF_PH1B;
    float* ph2a  = scratch + OFF_PH2A;
    float* ph2b  = scratch + OFF_PH2B;
    float* part  = scratch + OFF_PART;

    float* rec_out  = (float*)d_out;
    float* pred_out = rec_out + (size_t)NB * NT * NN;

    const int ENC_SMEM = (8 * 132 + 1024 + 128 * 132 + 16 * 68) * 4;
    const int DEC_SMEM = (16 * 132 * 2 + 128 * 132 + 128 * 8) * 4;
    cudaFuncSetAttribute(k_enc2, cudaFuncAttributeMaxDynamicSharedMemorySize, ENC_SMEM);
    cudaFuncSetAttribute(k_dec_rec2, cudaFuncAttributeMaxDynamicSharedMemorySize, DEC_SMEM);
    cudaFuncSetAttribute(k_dec_pred2, cudaFuncAttributeMaxDynamicSharedMemorySize, DEC_SMEM);

    // ---- preprocessing ----
    k_norm_adj<<<NN, 256>>>(adj, a1, a2);
    k_comb_w<<<(11 * 64 * 64 + 255) / 256, 256>>>(cw[0], cw[1], cw[2], cw[3], cw[4], cw[5],
                                                  cb[0], cb[1], cb[2], cb[3], cb[4], cb[5],
                                                  wcT, bsum);
    k_comb_g<<<80, 256>>>(g1_w, g1_b, g2_w, g2_b, ec, eb);

    // ---- encoder ----
    k_enc2<<<dim3(8, FREQ, NB), 256, ENC_SMEM>>>(x_diff, enc_w1, enc_b1, enc_w2, enc_b2, res);

    // ---- rec-path stconv ----
    k_tconv<<<dim3(8, NB * TREC), 256>>>(res, wcT, bsum, conv);
    k_prop128<<<dim3(8, NB * TREC / 2, 2), 256>>>(a1, a2, conv, conv, h1a, h1b);
    k_prop128<<<dim3(8, NB * TREC / 2, 2), 256>>>(a1, a2, h1a, h1b, h2a, h2b);
    k_combine<<<dim3(8, NB * TREC), 256>>>(conv, h1a, h2a, h1b, h2b, ec, eb,
                                           res, stout,
                                           TREC, FREQ, 0,
                                           TREC, TREC, 0);
    // ---- rec decoder ----
    k_dec_rec2<<<dim3(8, FREQ, NB), 256, DEC_SMEM>>>(res, stout, dec_w1, dec_b1,
                                                     dec_w2, dec_b2, rec_out);

    // ---- autoregressive loop ----
    k_cur_init<<<4096, 256>>>(res, cur);
    for (int s = 0; s < NSTEP; s++) {
        k_tcl<<<64, 256>>>(cur, wcT, bsum, tcl, s);
        k_prop_sk<<<dim3(8, 4, 8), 256>>>(a1, a2, tcl, tcl, part);
        k_reduce4<<<512, 256>>>(part, ph1a, ph1b);
        k_prop_sk<<<dim3(8, 4, 8), 256>>>(a1, a2, ph1a, ph1b, part);
        k_reduce4<<<512, 256>>>(part, ph2a, ph2b);
        k_combine<<<dim3(8, NB), 256>>>(tcl, ph1a, ph2a, ph1b, ph2b, ec, eb,
                                        cur, cur,
                                        1, 23, s + 10,
                                        1, 23, s + 11);
    }
    // ---- pred decoder ----
    k_dec_pred2<<<dim3(8, NSTEP, NB), 256, DEC_SMEM>>>(cur, dec_w1, dec_b1,
                                                       dec_w2, dec_b2, pred_out);
}

// round 8
// speedup vs baseline: 2.3593x; 1.4588x over previous
#include <cuda_runtime.h>
#include <cuda_bf16.h>
#include <cstdint>

// ---------------- problem constants ----------------
#define NB   8
#define NT   336
#define NN   1024
#define FREQ 42
#define SEG  8
#define TREC 41
#define NSTEP 12
#define MAXK 11
#define ALPHA 0.05f
#define BETA  0.95f

// ---------------- scratch layout (floats) ----------------
static const size_t OFF_WCT  = 0;                        // 11*64*64
static const size_t OFF_BSUM = OFF_WCT  + 45056;         // 64
static const size_t OFF_EC   = OFF_BSUM + 64;            // 5*64*64
static const size_t OFF_EB   = OFF_EC   + 20480;         // 64
static const size_t OFF_A1H  = OFF_EB   + 64;            // bf16 1024^2 = 524288 fl
static const size_t OFF_A1L  = OFF_A1H  + 524288;
static const size_t OFF_A2H  = OFF_A1L  + 524288;
static const size_t OFF_A2L  = OFF_A2H  + 524288;
static const size_t OFF_RES  = OFF_A2L  + 524288;        // 8*42*1024*64
static const size_t OFF_CONV = OFF_RES  + 22020096;      // 8*41*1024*64
static const size_t OFF_H1A  = OFF_CONV + 21495808;
static const size_t OFF_H2A  = OFF_H1A  + 21495808;
static const size_t OFF_H1B  = OFF_H2A  + 21495808;
static const size_t OFF_H2B  = OFF_H1B  + 21495808;
static const size_t OFF_STOUT= OFF_H2B  + 21495808;
static const size_t OFF_CUR  = OFF_STOUT+ 21495808;      // 8*23*1024*64
static const size_t OFF_TCL  = OFF_CUR  + 12058624;      // 8*1024*64
static const size_t OFF_PH1A = OFF_TCL  + 524288;
static const size_t OFF_PH1B = OFF_PH1A + 524288;
static const size_t OFF_PH2A = OFF_PH1B + 524288;
static const size_t OFF_PH2B = OFF_PH2A + 524288;
// bf16 transposed planes (sizes in floats = bf16count/2)
static const size_t OFF_CTH  = OFF_PH2B + 524288;        // 328*64*1024 bf16
static const size_t OFF_CTL  = OFF_CTH  + 10747904;
static const size_t OFF_H1ATH= OFF_CTL  + 10747904;
static const size_t OFF_H1ATL= OFF_H1ATH+ 10747904;
static const size_t OFF_H1BTH= OFF_H1ATL+ 10747904;
static const size_t OFF_H1BTL= OFF_H1BTH+ 10747904;
static const size_t OFF_TCTH = OFF_H1BTL+ 10747904;      // 8*64*1024 bf16
static const size_t OFF_TCTL = OFF_TCTH + 262144;
static const size_t OFF_P1ATH= OFF_TCTL + 262144;
static const size_t OFF_P1ATL= OFF_P1ATH+ 262144;
static const size_t OFF_P1BTH= OFF_P1ATL+ 262144;
static const size_t OFF_P1BTL= OFF_P1BTH+ 262144;
static const size_t SCRATCH_TOTAL = OFF_P1BTL + 262144;

__device__ float g_scratch[SCRATCH_TOTAL];

// ================= mma.sync helpers (sm_80+ baseline PTX) =================
__device__ __forceinline__ uint32_t smem_u32(const void* p) {
    uint32_t a;
    asm("{ .reg .u64 t; cvta.to.shared.u64 t, %1; cvt.u32.u64 %0, t; }" : "=r"(a) : "l"(p));
    return a;
}
__device__ __forceinline__ void mma16816(float* c, const uint32_t* a, const uint32_t* b) {
    asm volatile("mma.sync.aligned.m16n8k16.row.col.f32.bf16.bf16.f32 "
        "{%0,%1,%2,%3}, {%4,%5,%6,%7}, {%8,%9}, {%0,%1,%2,%3};"
        : "+f"(c[0]), "+f"(c[1]), "+f"(c[2]), "+f"(c[3])
        : "r"(a[0]), "r"(a[1]), "r"(a[2]), "r"(a[3]), "r"(b[0]), "r"(b[1]));
}
__device__ __forceinline__ void ldsm4(uint32_t* r, uint32_t addr) {
    asm volatile("ldmatrix.sync.aligned.m8n8.x4.shared.b16 {%0,%1,%2,%3}, [%4];"
        : "=r"(r[0]), "=r"(r[1]), "=r"(r[2]), "=r"(r[3]) : "r"(addr));
}

// ================= GEMM64 chunk macro (FFMA path) =================
#define GEMM64_CHUNK(ASRC, BSRC) do {                                          \
    const float* _as = (ASRC); const float* _bs = (BSRC);                      \
    for (int k0 = 0; k0 < 64; k0 += 16) {                                      \
        _Pragma("unroll")                                                      \
        for (int i = 0; i < 2; i++) {                                          \
            int li = tid + i * 256;                                            \
            int m = li & 127, k4 = li >> 7;                                    \
            float4 v = *(const float4*)&_as[(size_t)m * 64 + k0 + k4 * 4];     \
            As[k4*4+0][m] = v.x; As[k4*4+1][m] = v.y;                          \
            As[k4*4+2][m] = v.z; As[k4*4+3][m] = v.w;                          \
        }                                                                      \
        {                                                                      \
            int kk = tid >> 4, n4 = (tid & 15) * 4;                            \
            *(float4*)&Bs[kk][n4] =                                            \
                *(const float4*)&_bs[(size_t)(k0 + kk) * 64 + n4];             \
        }                                                                      \
        __syncthreads();                                                       \
        _Pragma("unroll")                                                      \
        for (int k = 0; k < 16; k++) {                                         \
            float a_[8], b_[4];                                                \
            *(float4*)&a_[0] = *(const float4*)&As[k][ty * 4];                 \
            *(float4*)&a_[4] = *(const float4*)&As[k][64 + ty * 4];            \
            *(float4*)&b_[0] = *(const float4*)&Bs[k][tx * 4];                 \
            _Pragma("unroll")                                                  \
            for (int i = 0; i < 8; i++) {                                      \
                _Pragma("unroll")                                              \
                for (int j = 0; j < 4; j++)                                    \
                    acc[i][j] = fmaf(a_[i], b_[j], acc[i][j]);                 \
            }                                                                  \
        }                                                                      \
        __syncthreads();                                                       \
    }                                                                          \
} while (0)

// ================= adjacency normalization -> bf16 hi/lo planes =================
__global__ void k_norm_adj(const float* __restrict__ adj,
                           __nv_bfloat16* __restrict__ a1h, __nv_bfloat16* __restrict__ a1l,
                           __nv_bfloat16* __restrict__ a2h, __nv_bfloat16* __restrict__ a2l) {
    int v = blockIdx.x;
    int tid = threadIdx.x;
    __shared__ float r1[256], r2[256];
    float s1 = 0.f, s2 = 0.f;
    for (int n = tid; n < NN; n += 256) {
        s1 += adj[(size_t)v * NN + n];
        s2 += adj[(size_t)n * NN + v];
    }
    r1[tid] = s1; r2[tid] = s2;
    __syncthreads();
    for (int off = 128; off > 0; off >>= 1) {
        if (tid < off) { r1[tid] += r1[tid + off]; r2[tid] += r2[tid + off]; }
        __syncthreads();
    }
    float inv1 = 1.f / (r1[0] + 1.f);
    float inv2 = 1.f / (r2[0] + 1.f);
    for (int n = tid; n < NN; n += 256) {
        float d = (n == v) ? 1.f : 0.f;
        float v1 = (adj[(size_t)v * NN + n] + d) * inv1;
        float v2 = (adj[(size_t)n * NN + v] + d) * inv2;
        __nv_bfloat16 h1 = __float2bfloat16(v1);
        __nv_bfloat16 h2 = __float2bfloat16(v2);
        a1h[(size_t)v * NN + n] = h1;
        a1l[(size_t)v * NN + n] = __float2bfloat16(v1 - __bfloat162float(h1));
        a2h[(size_t)v * NN + n] = h2;
        a2l[(size_t)v * NN + n] = __float2bfloat16(v2 - __bfloat162float(h2));
    }
}

// ================= transpose+split: rm fp32 [R][1024][64] -> T bf16 [R][64][1024] ====
__global__ void __launch_bounds__(256) k_tsplit(const float* __restrict__ in,
        __nv_bfloat16* __restrict__ oh, __nv_bfloat16* __restrict__ ol) {
    int n0 = blockIdx.x * 128;
    int r  = blockIdx.y;
    __shared__ float t[128][65];
    int tid = threadIdx.x;
    const float* src = in + (size_t)r * 65536 + (size_t)n0 * 64;
#pragma unroll
    for (int it = 0; it < 8; it++) {
        int li = tid + it * 256;
        int n = li >> 4, d4 = (li & 15) * 4;
        float4 v = *(const float4*)&src[(size_t)n * 64 + d4];
        t[n][d4] = v.x; t[n][d4+1] = v.y; t[n][d4+2] = v.z; t[n][d4+3] = v.w;
    }
    __syncthreads();
    int d = tid >> 2, nc = (tid & 3) * 32;
    size_t ob = (size_t)r * 65536 + (size_t)d * 1024 + n0 + nc;
#pragma unroll
    for (int q = 0; q < 32; q += 2) {
        float v0 = t[nc + q][d], v1 = t[nc + q + 1][d];
        __nv_bfloat16 h0 = __float2bfloat16(v0), h1 = __float2bfloat16(v1);
        __nv_bfloat16 l0 = __float2bfloat16(v0 - __bfloat162float(h0));
        __nv_bfloat16 l1 = __float2bfloat16(v1 - __bfloat162float(h1));
        *(__nv_bfloat162*)&oh[ob + q] = __halves2bfloat162(h0, h1);
        *(__nv_bfloat162*)&ol[ob + q] = __halves2bfloat162(l0, l1);
    }
}

// ================= mma.sync prop: D[128m,64d] = A[m,n] @ H[n,d] (B = H^T planes) ====
// grid (8 m-tiles, nbt, 2 dirs), 256 threads (8 warps, 4x2 warp grid, 32x32/warp)
#define SAS 72   // smem row stride in bf16
__global__ void __launch_bounds__(256)
k_prop_mma(const __nv_bfloat16* __restrict__ a1h, const __nv_bfloat16* __restrict__ a1l,
           const __nv_bfloat16* __restrict__ a2h, const __nv_bfloat16* __restrict__ a2l,
           const __nv_bfloat16* __restrict__ bT0h, const __nv_bfloat16* __restrict__ bT0l,
           const __nv_bfloat16* __restrict__ bT1h, const __nv_bfloat16* __restrict__ bT1l,
           float* __restrict__ out0, float* __restrict__ out1,
           __nv_bfloat16* __restrict__ oT0h, __nv_bfloat16* __restrict__ oT0l,
           __nv_bfloat16* __restrict__ oT1h, __nv_bfloat16* __restrict__ oT1l,
           int writeT) {
    int m0 = blockIdx.x * 128;
    int bt = blockIdx.y;
    int dir = blockIdx.z;
    const __nv_bfloat16* Ah = dir ? a2h : a1h;
    const __nv_bfloat16* Al = dir ? a2l : a1l;
    const __nv_bfloat16* Bh = (dir ? bT1h : bT0h) + (size_t)bt * 65536;
    const __nv_bfloat16* Bl = (dir ? bT1l : bT0l) + (size_t)bt * 65536;
    float* orm = (dir ? out1 : out0) + (size_t)bt * 65536;

    extern __shared__ __nv_bfloat16 sb[];
    __nv_bfloat16* sAh = sb;                       // [128][SAS]
    __nv_bfloat16* sAl = sb + 128 * SAS;
    __nv_bfloat16* sBh = sb + 2 * 128 * SAS;       // [64][SAS]
    __nv_bfloat16* sBl = sBh + 64 * SAS;
    uint32_t aAh = smem_u32(sAh), aAl = smem_u32(sAl);
    uint32_t aBh = smem_u32(sBh), aBl = smem_u32(sBl);

    int tid = threadIdx.x, lane = tid & 31, wid = tid >> 5;
    int wm = wid >> 1, wn = wid & 1;
    int lr = lane & 15;              // ldmatrix row within 16-row tile
    int lc = (lane >> 4) * 8;        // ldmatrix col half

    float acc[2][4][4];
#pragma unroll
    for (int i = 0; i < 2; i++)
#pragma unroll
        for (int j = 0; j < 4; j++)
#pragma unroll
            for (int q = 0; q < 4; q++) acc[i][j][q] = 0.f;

    for (int c = 0; c < 16; c++) {
        int k0 = c * 64;
#pragma unroll
        for (int it = 0; it < 4; it++) {
            int li = tid + it * 256;
            int row = li >> 3, c8 = li & 7;
            *(uint4*)&sAh[row * SAS + c8 * 8] =
                *(const uint4*)&Ah[(size_t)(m0 + row) * 1024 + k0 + c8 * 8];
            *(uint4*)&sAl[row * SAS + c8 * 8] =
                *(const uint4*)&Al[(size_t)(m0 + row) * 1024 + k0 + c8 * 8];
        }
#pragma unroll
        for (int it = 0; it < 2; it++) {
            int li = tid + it * 256;
            int row = li >> 3, c8 = li & 7;
            *(uint4*)&sBh[row * SAS + c8 * 8] =
                *(const uint4*)&Bh[(size_t)row * 1024 + k0 + c8 * 8];
            *(uint4*)&sBl[row * SAS + c8 * 8] =
                *(const uint4*)&Bl[(size_t)row * 1024 + k0 + c8 * 8];
        }
        __syncthreads();

#pragma unroll
        for (int pass = 0; pass < 3; pass++) {
            uint32_t aA = (pass == 2) ? aAl : aAh;
            uint32_t aB = (pass == 1) ? aBl : aBh;
            uint32_t af[2][4][4];
#pragma unroll
            for (int mi = 0; mi < 2; mi++)
#pragma unroll
                for (int kk = 0; kk < 4; kk++)
                    ldsm4(af[mi][kk],
                          aA + (uint32_t)(((wm * 32 + mi * 16 + lr) * SAS
                                           + kk * 16 + lc) * 2));
            uint32_t bfr[4][4][2];
#pragma unroll
            for (int np = 0; np < 2; np++)
#pragma unroll
                for (int kk = 0; kk < 4; kk++) {
                    uint32_t r[4];
                    ldsm4(r, aB + (uint32_t)(((wn * 32 + np * 16 + lr) * SAS
                                              + kk * 16 + lc) * 2));
                    bfr[2*np][kk][0]   = r[0]; bfr[2*np][kk][1]   = r[2];
                    bfr[2*np+1][kk][0] = r[1]; bfr[2*np+1][kk][1] = r[3];
                }
#pragma unroll
            for (int mi = 0; mi < 2; mi++)
#pragma unroll
                for (int nf = 0; nf < 4; nf++)
#pragma unroll
                    for (int kk = 0; kk < 4; kk++)
                        mma16816(acc[mi][nf], af[mi][kk], bfr[nf][kk]);
        }
        __syncthreads();
    }

    // epilogue: fp32 row-major out + optional bf16 hi/lo transposed planes
    __nv_bfloat16* oTh = (dir ? oT1h : oT0h) + (size_t)bt * 65536;
    __nv_bfloat16* oTl = (dir ? oT1l : oT0l) + (size_t)bt * 65536;
#pragma unroll
    for (int mi = 0; mi < 2; mi++) {
        int r0 = m0 + wm * 32 + mi * 16 + (lane >> 2);
#pragma unroll
        for (int nf = 0; nf < 4; nf++) {
            int d0 = wn * 32 + nf * 8 + (lane & 3) * 2;
            float2 v0 = make_float2(acc[mi][nf][0], acc[mi][nf][1]);
            float2 v1 = make_float2(acc[mi][nf][2], acc[mi][nf][3]);
            *(float2*)&orm[(size_t)r0 * 64 + d0]       = v0;
            *(float2*)&orm[(size_t)(r0 + 8) * 64 + d0] = v1;
            if (writeT) {
#pragma unroll
                for (int q = 0; q < 4; q++) {
                    float v = acc[mi][nf][q];
                    int mm = r0 + (q >= 2 ? 8 : 0);
                    int dd = d0 + (q & 1);
                    __nv_bfloat16 h = __float2bfloat16(v);
                    oTh[(size_t)dd * 1024 + mm] = h;
                    oTl[(size_t)dd * 1024 + mm] =
                        __float2bfloat16(v - __bfloat162float(h));
                }
            }
        }
    }
}

// ================= combine conv weights =================
__global__ void k_comb_w(const float* w0, const float* w1, const float* w2,
                         const float* w3, const float* w4, const float* w5,
                         const float* cb0, const float* cb1, const float* cb2,
                         const float* cb3, const float* cb4, const float* cb5,
                         float* __restrict__ wcT, float* __restrict__ bsum) {
    int idx = blockIdx.x * 256 + threadIdx.x;
    if (idx >= 11 * 64 * 64) return;
    int o = idx & 63;
    int c = (idx >> 6) & 63;
    int dt = idx >> 12;
    int dv = dt - 5;
    int ad = dv < 0 ? -dv : dv;
    const float* ws[6] = {w0, w1, w2, w3, w4, w5};
    float acc = 0.f;
    for (int i = ad; i < 6; i++) {
        int K = 2 * i + 1;
        acc += ws[i][(size_t)(o * 64 + c) * K + (dv + i)];
    }
    wcT[((size_t)dt * 64 + c) * 64 + o] = acc;
    if (dt == 0 && c == 0)
        bsum[o] = cb0[o] + cb1[o] + cb2[o] + cb3[o] + cb4[o] + cb5[o];
}

// ================= combine mixprop weights =================
__global__ void k_comb_g(const float* __restrict__ g1w, const float* __restrict__ g1b,
                         const float* __restrict__ g2w, const float* __restrict__ g2b,
                         float* __restrict__ ec, float* __restrict__ eb) {
    int idx = blockIdx.x * 256 + threadIdx.x;
    if (idx >= 5 * 4096) return;
    int term = idx >> 12;
    int co = idx & 4095;
    float v;
    if (term == 0) {
        v = g1w[co] + ALPHA * (g1w[4096 + co] + g1w[8192 + co])
          + g2w[co] + ALPHA * (g2w[4096 + co] + g2w[8192 + co]);
    } else if (term == 1) {
        v = BETA * g1w[4096 + co] + ALPHA * BETA * g1w[8192 + co];
    } else if (term == 2) {
        v = BETA * BETA * g1w[8192 + co];
    } else if (term == 3) {
        v = BETA * g2w[4096 + co] + ALPHA * BETA * g2w[8192 + co];
    } else {
        v = BETA * BETA * g2w[8192 + co];
    }
    ec[idx] = v;
    if (idx < 64) eb[idx] = g1b[idx] + g2b[idx];
}

// ================= encoder MLP (two-stage tiled GEMM) =================
__global__ void __launch_bounds__(256) k_enc2(const float* __restrict__ x,
        const float* __restrict__ w1, const float* __restrict__ b1,
        const float* __restrict__ w2, const float* __restrict__ b2,
        float* __restrict__ out) {
    extern __shared__ float sm[];
    float* xst = sm;
    float* w1s = xst + 8 * 132;
    float* hst = w1s + 1024;
    float* Bs  = hst + 128 * 132;
    int n0 = blockIdx.x * 128;
    int f  = blockIdx.y;
    int b  = blockIdx.z;
    int tid = threadIdx.x, tx = tid & 15, ty = tid >> 4;

#pragma unroll
    for (int it = 0; it < 4; it++) {
        int li = tid + it * 256;
        int s = li >> 7, m = li & 127;
        xst[s * 132 + m] = x[((size_t)b * NT + f * SEG + s) * NN + n0 + m];
        w1s[li] = w1[li];
    }
    __syncthreads();

    float acc1[8][8] = {};
#pragma unroll
    for (int k = 0; k < 8; k++) {
        float a_[8], b_[8];
        *(float4*)&a_[0] = *(const float4*)&w1s[k * 128 + ty * 4];
        *(float4*)&a_[4] = *(const float4*)&w1s[k * 128 + 64 + ty * 4];
        *(float4*)&b_[0] = *(const float4*)&xst[k * 132 + tx * 4];
        *(float4*)&b_[4] = *(const float4*)&xst[k * 132 + 64 + tx * 4];
#pragma unroll
        for (int i = 0; i < 8; i++)
#pragma unroll
            for (int j = 0; j < 8; j++)
                acc1[i][j] = fmaf(a_[i], b_[j], acc1[i][j]);
    }
#pragma unroll
    for (int i = 0; i < 8; i++) {
        int j = (i < 4) ? ty * 4 + i : 64 + ty * 4 + (i - 4);
        float bb = b1[j];
        float4 v0, v1;
        v0.x = fmaxf(acc1[i][0] + bb, 0.f); v0.y = fmaxf(acc1[i][1] + bb, 0.f);
        v0.z = fmaxf(acc1[i][2] + bb, 0.f); v0.w = fmaxf(acc1[i][3] + bb, 0.f);
        v1.x = fmaxf(acc1[i][4] + bb, 0.f); v1.y = fmaxf(acc1[i][5] + bb, 0.f);
        v1.z = fmaxf(acc1[i][6] + bb, 0.f); v1.w = fmaxf(acc1[i][7] + bb, 0.f);
        *(float4*)&hst[j * 132 + tx * 4]      = v0;
        *(float4*)&hst[j * 132 + 64 + tx * 4] = v1;
    }
    __syncthreads();

    float acc2[8][4] = {};
    for (int k0 = 0; k0 < 128; k0 += 16) {
        {
            int kk = tid >> 4, n4 = (tid & 15) * 4;
            *(float4*)&Bs[kk * 68 + n4] = *(const float4*)&w2[(size_t)(k0 + kk) * 64 + n4];
        }
        __syncthreads();
#pragma unroll
        for (int k = 0; k < 16; k++) {
            float a_[8], b_[4];
            *(float4*)&a_[0] = *(const float4*)&hst[(k0 + k) * 132 + ty * 4];
            *(float4*)&a_[4] = *(const float4*)&hst[(k0 + k) * 132 + 64 + ty * 4];
            *(float4*)&b_[0] = *(const float4*)&Bs[k * 68 + tx * 4];
#pragma unroll
            for (int i = 0; i < 8; i++)
#pragma unroll
                for (int j = 0; j < 4; j++)
                    acc2[i][j] = fmaf(a_[i], b_[j], acc2[i][j]);
        }
        __syncthreads();
    }
    float4 b2v = *(const float4*)&b2[tx * 4];
#pragma unroll
    for (int i = 0; i < 8; i++) {
        int m = n0 + ((i < 4) ? ty * 4 + i : 64 + ty * 4 + (i - 4));
        float4 v;
        v.x = acc2[i][0] + b2v.x; v.y = acc2[i][1] + b2v.y;
        v.z = acc2[i][2] + b2v.z; v.w = acc2[i][3] + b2v.w;
        *(float4*)&out[(((size_t)b * FREQ + f) * NN + m) * 64 + tx * 4] = v;
    }
}

// ================= decoder MLP stage macros =================
#define DEC_STAGE1(SRC) do {                                                   \
    float acc1[8][8] = {};                                                     \
    for (int k0 = 0; k0 < 64; k0 += 16) {                                      \
        _Pragma("unroll")                                                      \
        for (int it = 0; it < 2; it++) {                                       \
            int f4 = tid + it * 256;                                           \
            int kk = f4 >> 5, j4 = (f4 & 31) * 4;                              \
            *(float4*)&As1[kk * 132 + j4] =                                    \
                *(const float4*)&w1[(size_t)(k0 + kk) * 128 + j4];             \
        }                                                                      \
        _Pragma("unroll")                                                      \
        for (int it = 0; it < 2; it++) {                                       \
            int li = tid + it * 256;                                           \
            int m = li & 127, k4 = li >> 7;                                    \
            float4 v = *(const float4*)&(SRC)[(size_t)m * 64 + k0 + k4 * 4];   \
            Bs1[(k4*4+0)*132 + m] = v.x; Bs1[(k4*4+1)*132 + m] = v.y;          \
            Bs1[(k4*4+2)*132 + m] = v.z; Bs1[(k4*4+3)*132 + m] = v.w;          \
        }                                                                      \
        __syncthreads();                                                       \
        _Pragma("unroll")                                                      \
        for (int k = 0; k < 16; k++) {                                         \
            float a_[8], b_[8];                                                \
            *(float4*)&a_[0] = *(const float4*)&As1[k * 132 + ty * 4];         \
            *(float4*)&a_[4] = *(const float4*)&As1[k * 132 + 64 + ty * 4];    \
            *(float4*)&b_[0] = *(const float4*)&Bs1[k * 132 + tx * 4];         \
            *(float4*)&b_[4] = *(const float4*)&Bs1[k * 132 + 64 + tx * 4];    \
            _Pragma("unroll")                                                  \
            for (int i = 0; i < 8; i++)                                        \
                _Pragma("unroll")                                              \
                for (int j = 0; j < 8; j++)                                    \
                    acc1[i][j] = fmaf(a_[i], b_[j], acc1[i][j]);               \
        }                                                                      \
        __syncthreads();                                                       \
    }                                                                          \
    _Pragma("unroll")                                                          \
    for (int i = 0; i < 8; i++) {                                              \
        int j = (i < 4) ? ty * 4 + i : 64 + ty * 4 + (i - 4);                  \
        float bb = b1[j];                                                      \
        float4 v0, v1;                                                         \
        v0.x = fmaxf(acc1[i][0] + bb, 0.f); v0.y = fmaxf(acc1[i][1] + bb, 0.f);\
        v0.z = fmaxf(acc1[i][2] + bb, 0.f); v0.w = fmaxf(acc1[i][3] + bb, 0.f);\
        v1.x = fmaxf(acc1[i][4] + bb, 0.f); v1.y = fmaxf(acc1[i][5] + bb, 0.f);\
        v1.z = fmaxf(acc1[i][6] + bb, 0.f); v1.w = fmaxf(acc1[i][7] + bb, 0.f);\
        *(float4*)&hst[j * 132 + tx * 4]      = v0;                            \
        *(float4*)&hst[j * 132 + 64 + tx * 4] = v1;                            \
    }                                                                          \
    __syncthreads();                                                           \
} while (0)

#define DEC_STAGE2(A4, M_, SG_) do {                                           \
    M_ = tid >> 1; SG_ = tid & 1;                                              \
    A4[0] = b2[SG_ * 4 + 0]; A4[1] = b2[SG_ * 4 + 1];                          \
    A4[2] = b2[SG_ * 4 + 2]; A4[3] = b2[SG_ * 4 + 3];                          \
    _Pragma("unroll 4")                                                        \
    for (int j = 0; j < 128; j++) {                                            \
        float h = hst[j * 132 + M_];                                           \
        float4 w = *(const float4*)&w2s[j * 8 + SG_ * 4];                      \
        A4[0] = fmaf(h, w.x, A4[0]); A4[1] = fmaf(h, w.y, A4[1]);              \
        A4[2] = fmaf(h, w.z, A4[2]); A4[3] = fmaf(h, w.w, A4[3]);              \
    }                                                                          \
} while (0)

// ================= decoder MLP for rec =================
__global__ void __launch_bounds__(256) k_dec_rec2(const float* __restrict__ res,
        const float* __restrict__ stout,
        const float* __restrict__ w1, const float* __restrict__ b1,
        const float* __restrict__ w2, const float* __restrict__ b2,
        float* __restrict__ out) {
    extern __shared__ float sm[];
    float* As1 = sm;
    float* Bs1 = As1 + 16 * 132;
    float* hst = Bs1 + 16 * 132;
    float* w2s = hst + 128 * 132;
    int n0 = blockIdx.x * 128;
    int f  = blockIdx.y;
    int b  = blockIdx.z;
    int tid = threadIdx.x, tx = tid & 15, ty = tid >> 4;
    const float* src = (f == 0)
        ? &res[(((size_t)b * FREQ) * NN + n0) * 64]
        : &stout[(((size_t)b * TREC + f - 1) * NN + n0) * 64];
#pragma unroll
    for (int it = 0; it < 4; it++) w2s[tid + it * 256] = w2[tid + it * 256];
    DEC_STAGE1(src);
    float a4[4];
    int m, sg;
    DEC_STAGE2(a4, m, sg);
#pragma unroll
    for (int q = 0; q < 4; q++) {
        int s = sg * 4 + q;
        out[((size_t)b * NT + f * SEG + s) * NN + n0 + m] = a4[q];
    }
}

// ================= decoder MLP for pred =================
__global__ void __launch_bounds__(256) k_dec_pred2(const float* __restrict__ cur,
        const float* __restrict__ w1, const float* __restrict__ b1,
        const float* __restrict__ w2, const float* __restrict__ b2,
        float* __restrict__ out) {
    extern __shared__ float sm[];
    float* As1 = sm;
    float* Bs1 = As1 + 16 * 132;
    float* hst = Bs1 + 16 * 132;
    float* w2s = hst + 128 * 132;
    int n0 = blockIdx.x * 128;
    int t  = blockIdx.y;
    int b  = blockIdx.z;
    int tid = threadIdx.x, tx = tid & 15, ty = tid >> 4;
    const float* src = &cur[(((size_t)b * 23 + MAXK + t) * NN + n0) * 64];
#pragma unroll
    for (int it = 0; it < 4; it++) w2s[tid + it * 256] = w2[tid + it * 256];
    DEC_STAGE1(src);
    float a4[4];
    int m, sg;
    DEC_STAGE2(a4, m, sg);
    float4 v = make_float4(a4[0], a4[1], a4[2], a4[3]);
    *(float4*)&out[(size_t)b * (NSTEP * SEG * NN) + (size_t)t * 8192
                   + (size_t)(n0 + m) * 8 + sg * 4] = v;
}

// ================= t_inception (rec path), 128x64 tiles =================
__global__ void __launch_bounds__(256) k_tconv(const float* __restrict__ res,
        const float* __restrict__ wcT, const float* __restrict__ bsum,
        float* __restrict__ out) {
    int m0 = blockIdx.x * 128;
    int bt = blockIdx.y;
    int b = bt / TREC, t = bt % TREC;
    __shared__ float As[16][132];
    __shared__ float Bs[16][68];
    int tid = threadIdx.x;
    int tx = tid & 15, ty = tid >> 4;
    float acc[8][4] = {};
    for (int dt = 0; dt < MAXK; dt++) {
        int ts = t + dt - 5;
        if (ts < 0 || ts >= TREC) continue;
        GEMM64_CHUNK(&res[(((size_t)b * FREQ + ts) * NN + m0) * 64],
                     &wcT[(size_t)dt * 4096]);
    }
    const float inv6 = 1.f / 6.f;
    float4 bsv = *(const float4*)&bsum[tx * 4];
    float bsa[4] = {bsv.x, bsv.y, bsv.z, bsv.w};
#pragma unroll
    for (int i = 0; i < 8; i++) {
        int m = m0 + (i < 4 ? ty * 4 + i : 60 + ty * 4 + i);
        float4 v;
        v.x = (acc[i][0] + bsa[0]) * inv6;
        v.y = (acc[i][1] + bsa[1]) * inv6;
        v.z = (acc[i][2] + bsa[2]) * inv6;
        v.w = (acc[i][3] + bsa[3]) * inv6;
        *(float4*)&out[((size_t)bt * NN + m) * 64 + tx * 4] = v;
    }
}

// ================= combine (5-term) + bias + residual =================
__global__ void __launch_bounds__(256) k_combine(const float* __restrict__ x,
        const float* __restrict__ s1, const float* __restrict__ s2,
        const float* __restrict__ t1, const float* __restrict__ t2,
        const float* __restrict__ ec, const float* __restrict__ eb,
        const float* __restrict__ resid, float* __restrict__ out,
        int rdiv, int rmul, int roff,
        int odiv, int omul, int ooff) {
    int m0 = blockIdx.x * 128;
    int bt = blockIdx.y;
    size_t base = (size_t)bt * (NN * 64) + (size_t)m0 * 64;
    __shared__ float As[16][132];
    __shared__ float Bs[16][68];
    int tid = threadIdx.x;
    int tx = tid & 15, ty = tid >> 4;
    float acc[8][4] = {};
    GEMM64_CHUNK(x  + base, ec);
    GEMM64_CHUNK(s1 + base, ec + 4096);
    GEMM64_CHUNK(s2 + base, ec + 8192);
    GEMM64_CHUNK(t1 + base, ec + 12288);
    GEMM64_CHUNK(t2 + base, ec + 16384);
    int rrow = (bt / rdiv) * rmul + (bt % rdiv) + roff;
    int orow = (bt / odiv) * omul + (bt % odiv) + ooff;
    float4 ebv = *(const float4*)&eb[tx * 4];
    float eba[4] = {ebv.x, ebv.y, ebv.z, ebv.w};
#pragma unroll
    for (int i = 0; i < 8; i++) {
        int m = m0 + (i < 4 ? ty * 4 + i : 60 + ty * 4 + i);
        float4 rv = *(const float4*)&resid[((size_t)rrow * NN + m) * 64 + tx * 4];
        float4 v;
        v.x = acc[i][0] + eba[0] + rv.x;
        v.y = acc[i][1] + eba[1] + rv.y;
        v.z = acc[i][2] + eba[2] + rv.z;
        v.w = acc[i][3] + eba[3] + rv.w;
        *(float4*)&out[((size_t)orow * NN + m) * 64 + tx * 4] = v;
    }
}

// ================= AR last-timestep inception, 128x64 tiles =================
__global__ void __launch_bounds__(256) k_tcl(const float* __restrict__ cur,
        const float* __restrict__ wcT, const float* __restrict__ bsum,
        float* __restrict__ out, int s) {
    int gm = blockIdx.x;
    int b  = gm >> 3;
    int m0 = (gm & 7) * 128;
    __shared__ float As[16][132];
    __shared__ float Bs[16][68];
    int tid = threadIdx.x;
    int tx = tid & 15, ty = tid >> 4;
    float acc[8][4] = {};
    for (int j = 0; j < 6; j++) {
        GEMM64_CHUNK(&cur[(((size_t)b * 23 + s + 5 + j) * NN + m0) * 64],
                     &wcT[(size_t)j * 4096]);
    }
    const float inv6 = 1.f / 6.f;
    float4 bsv = *(const float4*)&bsum[tx * 4];
    float bsa[4] = {bsv.x, bsv.y, bsv.z, bsv.w};
#pragma unroll
    for (int i = 0; i < 8; i++) {
        int m = m0 + (i < 4 ? ty * 4 + i : 60 + ty * 4 + i);
        float4 v;
        v.x = (acc[i][0] + bsa[0]) * inv6;
        v.y = (acc[i][1] + bsa[1]) * inv6;
        v.z = (acc[i][2] + bsa[2]) * inv6;
        v.w = (acc[i][3] + bsa[3]) * inv6;
        *(float4*)&out[((size_t)b * NN + m) * 64 + tx * 4] = v;
    }
}

// ================= AR cur-buffer init =================
__global__ void k_cur_init(const float* __restrict__ res, float* __restrict__ cur) {
    size_t total = (size_t)NB * MAXK * NN * 64;
    for (size_t idx = (size_t)blockIdx.x * blockDim.x + threadIdx.x; idx < total;
         idx += (size_t)gridDim.x * blockDim.x) {
        int d = idx & 63;
        int n = (idx >> 6) & 1023;
        int j = (int)((idx >> 16) % MAXK);
        int b = (int)(idx / ((size_t)MAXK << 16));
        cur[(((size_t)b * 23 + j) * NN + n) * 64 + d] =
            res[(((size_t)b * FREQ + 31 + j) * NN + n) * 64 + d];
    }
}

// ================= host launcher =================
extern "C" void kernel_launch(void* const* d_in, const int* in_sizes, int n_in,
                              void* d_out, int out_size) {
    (void)in_sizes; (void)n_in; (void)out_size;
    const float* x_diff = (const float*)d_in[0];
    const float* adj    = (const float*)d_in[1];
    const float* enc_w1 = (const float*)d_in[2];
    const float* enc_b1 = (const float*)d_in[3];
    const float* enc_w2 = (const float*)d_in[4];
    const float* enc_b2 = (const float*)d_in[5];
    const float* dec_w1 = (const float*)d_in[6];
    const float* dec_b1 = (const float*)d_in[7];
    const float* dec_w2 = (const float*)d_in[8];
    const float* dec_b2 = (const float*)d_in[9];
    const float* g1_w   = (const float*)d_in[10];
    const float* g1_b   = (const float*)d_in[11];
    const float* g2_w   = (const float*)d_in[12];
    const float* g2_b   = (const float*)d_in[13];
    const float* cw[6], *cb[6];
    for (int i = 0; i < 6; i++) {
        cw[i] = (const float*)d_in[14 + 2 * i];
        cb[i] = (const float*)d_in[15 + 2 * i];
    }

    float* scratch = nullptr;
    cudaGetSymbolAddress((void**)&scratch, g_scratch);
    float* wcT   = scratch + OFF_WCT;
    float* bsum  = scratch + OFF_BSUM;
    float* ec    = scratch + OFF_EC;
    float* eb    = scratch + OFF_EB;
    __nv_bfloat16* a1h = (__nv_bfloat16*)(scratch + OFF_A1H);
    __nv_bfloat16* a1l = (__nv_bfloat16*)(scratch + OFF_A1L);
    __nv_bfloat16* a2h = (__nv_bfloat16*)(scratch + OFF_A2H);
    __nv_bfloat16* a2l = (__nv_bfloat16*)(scratch + OFF_A2L);
    float* res   = scratch + OFF_RES;
    float* conv  = scratch + OFF_CONV;
    float* h1a   = scratch + OFF_H1A;
    float* h2a   = scratch + OFF_H2A;
    float* h1b   = scratch + OFF_H1B;
    float* h2b   = scratch + OFF_H2B;
    float* stout = scratch + OFF_STOUT;
    float* cur   = scratch + OFF_CUR;
    float* tcl   = scratch + OFF_TCL;
    float* ph1a  = scratch + OFF_PH1A;
    float* ph1b  = scratch + OFF_PH1B;
    float* ph2a  = scratch + OFF_PH2A;
    float* ph2b  = scratch + OFF_PH2B;
    __nv_bfloat16* cth   = (__nv_bfloat16*)(scratch + OFF_CTH);
    __nv_bfloat16* ctl   = (__nv_bfloat16*)(scratch + OFF_CTL);
    __nv_bfloat16* h1ath = (__nv_bfloat16*)(scratch + OFF_H1ATH);
    __nv_bfloat16* h1atl = (__nv_bfloat16*)(scratch + OFF_H1ATL);
    __nv_bfloat16* h1bth = (__nv_bfloat16*)(scratch + OFF_H1BTH);
    __nv_bfloat16* h1btl = (__nv_bfloat16*)(scratch + OFF_H1BTL);
    __nv_bfloat16* tcth  = (__nv_bfloat16*)(scratch + OFF_TCTH);
    __nv_bfloat16* tctl  = (__nv_bfloat16*)(scratch + OFF_TCTL);
    __nv_bfloat16* p1ath = (__nv_bfloat16*)(scratch + OFF_P1ATH);
    __nv_bfloat16* p1atl = (__nv_bfloat16*)(scratch + OFF_P1ATL);
    __nv_bfloat16* p1bth = (__nv_bfloat16*)(scratch + OFF_P1BTH);
    __nv_bfloat16* p1btl = (__nv_bfloat16*)(scratch + OFF_P1BTL);

    float* rec_out  = (float*)d_out;
    float* pred_out = rec_out + (size_t)NB * NT * NN;

    const int ENC_SMEM = (8 * 132 + 1024 + 128 * 132 + 16 * 68) * 4;
    const int DEC_SMEM = (16 * 132 * 2 + 128 * 132 + 128 * 8) * 4;
    const int PROP_SMEM = (2 * 128 * SAS + 2 * 64 * SAS) * 2;   // 55296 B
    cudaFuncSetAttribute(k_enc2, cudaFuncAttributeMaxDynamicSharedMemorySize, ENC_SMEM);
    cudaFuncSetAttribute(k_dec_rec2, cudaFuncAttributeMaxDynamicSharedMemorySize, DEC_SMEM);
    cudaFuncSetAttribute(k_dec_pred2, cudaFuncAttributeMaxDynamicSharedMemorySize, DEC_SMEM);
    cudaFuncSetAttribute(k_prop_mma, cudaFuncAttributeMaxDynamicSharedMemorySize, PROP_SMEM);

    // ---- preprocessing ----
    k_norm_adj<<<NN, 256>>>(adj, a1h, a1l, a2h, a2l);
    k_comb_w<<<(11 * 64 * 64 + 255) / 256, 256>>>(cw[0], cw[1], cw[2], cw[3], cw[4], cw[5],
                                                  cb[0], cb[1], cb[2], cb[3], cb[4], cb[5],
                                                  wcT, bsum);
    k_comb_g<<<80, 256>>>(g1_w, g1_b, g2_w, g2_b, ec, eb);

    // ---- encoder ----
    k_enc2<<<dim3(8, FREQ, NB), 256, ENC_SMEM>>>(x_diff, enc_w1, enc_b1, enc_w2, enc_b2, res);

    // ---- rec-path stconv ----
    k_tconv<<<dim3(8, NB * TREC), 256>>>(res, wcT, bsum, conv);
    k_tsplit<<<dim3(8, NB * TREC), 256>>>(conv, cth, ctl);
    k_prop_mma<<<dim3(8, NB * TREC, 2), 256, PROP_SMEM>>>(
        a1h, a1l, a2h, a2l, cth, ctl, cth, ctl,
        h1a, h1b, h1ath, h1atl, h1bth, h1btl, 1);
    k_prop_mma<<<dim3(8, NB * TREC, 2), 256, PROP_SMEM>>>(
        a1h, a1l, a2h, a2l, h1ath, h1atl, h1bth, h1btl,
        h2a, h2b, h1ath, h1atl, h1bth, h1btl, 0);
    k_combine<<<dim3(8, NB * TREC), 256>>>(conv, h1a, h2a, h1b, h2b, ec, eb,
                                           res, stout,
                                           TREC, FREQ, 0,
                                           TREC, TREC, 0);
    // ---- rec decoder ----
    k_dec_rec2<<<dim3(8, FREQ, NB), 256, DEC_SMEM>>>(res, stout, dec_w1, dec_b1,
                                                     dec_w2, dec_b2, rec_out);

    // ---- autoregressive loop ----
    k_cur_init<<<4096, 256>>>(res, cur);
    for (int s = 0; s < NSTEP; s++) {
        k_tcl<<<64, 256>>>(cur, wcT, bsum, tcl, s);
        k_tsplit<<<dim3(8, NB), 256>>>(tcl, tcth, tctl);
        k_prop_mma<<<dim3(8, NB, 2), 256, PROP_SMEM>>>(
            a1h, a1l, a2h, a2l, tcth, tctl, tcth, tctl,
            ph1a, ph1b, p1ath, p1atl, p1bth, p1btl, 1);
        k_prop_mma<<<dim3(8, NB, 2), 256, PROP_SMEM>>>(
            a1h, a1l, a2h, a2l, p1ath, p1atl, p1bth, p1btl,
            ph2a, ph2b, p1ath, p1atl, p1bth, p1btl, 0);
        k_combine<<<dim3(8, NB), 256>>>(tcl, ph1a, ph2a, ph1b, ph2b, ec, eb,
                                        cur, cur,
                                        1, 23, s + 10,
                                        1, 23, s + 11);
    }
    // ---- pred decoder ----
    k_dec_pred2<<<dim3(8, NSTEP, NB), 256, DEC_SMEM>>>(cur, dec_w1, dec_b1,
                                                       dec_w2, dec_b2, pred_out);
}